// round 5
// baseline (speedup 1.0000x reference)
#include <cuda_runtime.h>
#include <cuda_bf16.h>
#include <math.h>

#define N_    50000
#define E_    800000
#define G_    64
#define H_    4
#define C_    64
#define EDIM_ 16
#define NT_   8
#define NR_   6
#define NEG_  0.2f

#define NPAD  50176           // 1024*49
#define NBLK  196

// ---------------- scratch (device globals) ----------------
__device__ float4 g_hnt[NT_ * 64];
__device__ float4 g_asnt[NT_];
__device__ float4 g_adnt[NT_];
__device__ float4 g_ae0[NR_];
__device__ float4 g_ae1[NR_];
__device__ float  g_tab0[NT_*NT_*NR_*4];
__device__ float  g_x1f[N_ * 64];
__device__ uint4  g_h1b[N_ * 32];         // bf16 h1: [n][256 bf16] = 32 uint4/row
__device__ float4 g_as1[N_];
__device__ float4 g_ad1[N_];
__device__ float4 g_pool[1024];
__device__ float  g_cnt[64];
// CSR
__device__ int g_deg[NPAD];
__device__ int g_row[NPAD];
__device__ int g_cur[NPAD];
__device__ int g_adj[E_];                 // (ns<<19)|(etype<<16)|src

__device__ __forceinline__ float lrelu(float v) { return v > 0.f ? v : NEG_ * v; }
__device__ __forceinline__ float eluf(float v)  { return v > 0.f ? v : expm1f(v); }

__device__ __forceinline__ unsigned bf2_to_u32(__nv_bfloat162 b) {
    return *reinterpret_cast<unsigned*>(&b);
}
__device__ __forceinline__ __nv_bfloat162 u32_to_bf2(unsigned u) {
    return *reinterpret_cast<__nv_bfloat162*>(&u);
}

__device__ __forceinline__ void red_add_f4(float4* addr, float4 v) {
    asm volatile("red.global.add.v4.f32 [%0], {%1,%2,%3,%4};"
                 :: "l"(addr), "f"(v.x), "f"(v.y), "f"(v.z), "f"(v.w) : "memory");
}

// ---------------- zero small scratch ----------------
__global__ void zero_small() {
    int i = blockIdx.x * blockDim.x + threadIdx.x;
    if (i < NPAD) g_deg[i] = 0;
    if (i < 1024) g_pool[i] = make_float4(0.f, 0.f, 0.f, 0.f);
    if (i < 64)   g_cnt[i] = 0.f;
}

// ---------------- CSR build ----------------
__global__ void hist_kernel(const int* __restrict__ dst) {
    int e = blockIdx.x * blockDim.x + threadIdx.x;
    if (e < E_) atomicAdd(&g_deg[dst[e]], 1);
}

// single-block scan: 1024 threads, 49 elements each
__global__ void __launch_bounds__(1024) scan_kernel() {
    __shared__ int wsum[32];
    int t = threadIdx.x;
    int lane = t & 31, w = t >> 5;
    int base = t * 49;
    int s = 0;
#pragma unroll 7
    for (int i = 0; i < 49; i++) s += g_deg[base + i];
    int v = s;
#pragma unroll
    for (int off = 1; off < 32; off <<= 1) {
        int u = __shfl_up_sync(0xffffffffu, v, off);
        if (lane >= off) v += u;
    }
    if (lane == 31) wsum[w] = v;
    __syncthreads();
    if (w == 0) {
        int x = wsum[lane];
#pragma unroll
        for (int off = 1; off < 32; off <<= 1) {
            int u = __shfl_up_sync(0xffffffffu, x, off);
            if (lane >= off) x += u;
        }
        wsum[lane] = x;
    }
    __syncthreads();
    int off = v - s + (w > 0 ? wsum[w - 1] : 0);
#pragma unroll 7
    for (int i = 0; i < 49; i++) {
        int d = g_deg[base + i];
        g_row[base + i] = off;
        g_cur[base + i] = off;
        off += d;
    }
}

__global__ void scatter_kernel(const int* __restrict__ src, const int* __restrict__ dst,
                               const int* __restrict__ et, const int* __restrict__ ntype) {
    int e = blockIdx.x * blockDim.x + threadIdx.x;
    if (e >= E_) return;
    int d = dst[e];
    int s = src[e];
    int ns = __ldg(&ntype[s]);
    int pos = atomicAdd(&g_cur[d], 1);
    g_adj[pos] = (ns << 19) | (et[e] << 16) | s;
}

// ---------------- precompute type tables (14 blocks) ----------------
__global__ void prep_kernel(const float* __restrict__ node_emb,
                            const float* __restrict__ edge_emb,
                            const float* __restrict__ W0,
                            const float* __restrict__ We0,
                            const float* __restrict__ as0,
                            const float* __restrict__ ad0,
                            const float* __restrict__ ae0,
                            const float* __restrict__ We1,
                            const float* __restrict__ ae1) {
    int j = threadIdx.x;
    __shared__ float red_s[8];
    if (j < 8) red_s[j] = 0.f;
    __syncthreads();

    if (blockIdx.x < NT_) {
        int nt = blockIdx.x;
        float acc = 0.f;
        for (int k = 0; k < 64; k++) acc += node_emb[nt * 64 + k] * W0[k * 256 + j];
        ((float*)g_hnt)[nt * 256 + j] = acc;
        atomicAdd(&red_s[j >> 6],       acc * as0[j]);
        atomicAdd(&red_s[4 + (j >> 6)], acc * ad0[j]);
        __syncthreads();
        if (j < 4)      ((float*)g_asnt)[nt * 4 + j]       = red_s[j];
        else if (j < 8) ((float*)g_adnt)[nt * 4 + (j - 4)] = red_s[j];
    } else {
        int t = blockIdx.x - NT_;
        float h0 = 0.f, h1 = 0.f;
        for (int k = 0; k < EDIM_; k++) {
            float ev = edge_emb[t * EDIM_ + k];
            h0 += ev * We0[k * 256 + j];
            h1 += ev * We1[k * 256 + j];
        }
        atomicAdd(&red_s[j >> 6],       h0 * ae0[j]);
        atomicAdd(&red_s[4 + (j >> 6)], h1 * ae1[j]);
        __syncthreads();
        if (j < 4)      ((float*)g_ae0)[t * 4 + j]       = red_s[j];
        else if (j < 8) ((float*)g_ae1)[t * 4 + (j - 4)] = red_s[j];
    }
}

__global__ void prep2_kernel() {
    int idx = blockIdx.x * 256 + threadIdx.x;
    if (idx >= NT_*NT_*NR_*4) return;
    int h  = idx & 3;
    int r  = idx >> 2;
    int t  = r % 6;
    int r2 = r / 6;
    int ns = r2 & 7;
    int nd = r2 >> 3;
    float v = ((float*)g_asnt)[ns*4+h] + ((float*)g_adnt)[nd*4+h] + ((float*)g_ae0)[t*4+h];
    g_tab0[idx] = __expf(lrelu(v));
}

// ---------------- layer 0: warp per dst node (32 nodes/block) ----------------
__global__ void __launch_bounds__(1024) layer0_kernel(const int* __restrict__ ntype,
                                                      const float* __restrict__ b0) {
    __shared__ float s_hnt[NT_ * 256];
    __shared__ float s_tab[NT_*NT_*NR_*4];
    __shared__ float s_b0[64];
    __shared__ int   s_cnt[32][48];
    int tid = threadIdx.x;
    for (int i = tid; i < NT_ * 256; i += 1024) s_hnt[i] = ((float*)g_hnt)[i];
    for (int i = tid; i < NT_*NT_*NR_*4; i += 1024) s_tab[i] = g_tab0[i];
    if (tid < 64) s_b0[tid] = b0[tid];
    __syncthreads();

    int warp = tid >> 5, lane = tid & 31;
    int d = blockIdx.x * 32 + warp;
    if (d >= N_) return;

    if (lane < 24) { s_cnt[warp][lane] = 0; s_cnt[warp][lane + 24] = 0; }
    int nd = ntype[d];
    int start = g_row[d], deg = g_deg[d];
    __syncwarp();
    for (int k = lane; k < deg; k += 32) {
        int w = g_adj[start + k];
        int t = (w >> 16) & 7;
        int ns = (w >> 19) & 7;
        atomicAdd(&s_cnt[warp][ns * 6 + t], 1);
    }
    __syncwarp();

    int ns = lane >> 2, h = lane & 3;
    float A = 0.f;
#pragma unroll
    for (int t = 0; t < 6; t++)
        A += (float)s_cnt[warp][ns * 6 + t] * s_tab[((nd * 8 + ns) * 6 + t) * 4 + h];
    float den = A;
    den += __shfl_xor_sync(0xffffffffu, den, 4);
    den += __shfl_xor_sync(0xffffffffu, den, 8);
    den += __shfl_xor_sync(0xffffffffu, den, 16);
    float ainv = A / (den + 1e-16f);

    float v0 = 0.f, v1 = 0.f;
#pragma unroll
    for (int l2 = 0; l2 < 32; l2++) {
        float a = __shfl_sync(0xffffffffu, ainv, l2);
        int base = (l2 >> 2) * 256 + (l2 & 3) * 64;
        v0 += a * s_hnt[base + lane];
        v1 += a * s_hnt[base + lane + 32];
    }
    v0 = 0.25f * v0 + s_b0[lane];
    v1 = 0.25f * v1 + s_b0[lane + 32];
    g_x1f[d * 64 + lane]      = eluf(v0);
    g_x1f[d * 64 + lane + 32] = eluf(v1);
}

// ---------------- layer 1 GEMM + fused attn logits + bf16 pack ----------------
__global__ void __launch_bounds__(256) gemm_attn_kernel(const float* __restrict__ W1,
                                                        const float* __restrict__ att_src1,
                                                        const float* __restrict__ att_dst1) {
    extern __shared__ float smem[];
    float* sW    = smem;            // 16384
    float* sx    = smem + 16384;    // 4096
    float* s_as  = smem + 20480;    // 256
    float* s_ad  = smem + 20736;    // 256
    float* strns = smem + 20992;    // 8 warps * 256
    int tid = threadIdx.x;
    int n0 = blockIdx.x * 64;
    for (int i = tid; i < 16384; i += 256) sW[i] = W1[i];
    for (int i = tid; i < 4096; i += 256) {
        int m = i >> 6, k = i & 63;
        int n = n0 + m;
        sx[i] = (n < N_) ? g_x1f[n * 64 + k] : 0.f;
    }
    if (tid < 256) { s_as[tid] = att_src1[tid]; s_ad[tid] = att_dst1[tid]; }
    __syncthreads();
    int lane = tid & 31, ng = tid >> 5;
    float* sl = strns + ng * 256;
    float acc[8][8];
#pragma unroll
    for (int m = 0; m < 8; m++)
#pragma unroll
        for (int i = 0; i < 8; i++) acc[m][i] = 0.f;
    for (int k = 0; k < 64; k++) {
        float w[8];
#pragma unroll
        for (int i = 0; i < 8; i++) w[i] = sW[k * 256 + lane + 32 * i];
#pragma unroll
        for (int m = 0; m < 8; m++) {
            float xk = sx[(ng * 8 + m) * 64 + k];
#pragma unroll
            for (int i = 0; i < 8; i++) acc[m][i] += xk * w[i];
        }
    }
#pragma unroll
    for (int m = 0; m < 8; m++) {
        int n = n0 + ng * 8 + m;
        if (n >= N_) continue;
        // transpose via smem -> bf16 pack (lane owns cols lane*8..+7)
#pragma unroll
        for (int i = 0; i < 8; i++) sl[lane + 32 * i] = acc[m][i];
        __syncwarp();
        float4 u0 = *(float4*)&sl[lane * 8];
        float4 u1 = *(float4*)&sl[lane * 8 + 4];
        __syncwarp();
        uint4 pk;
        pk.x = bf2_to_u32(__float22bfloat162_rn(make_float2(u0.x, u0.y)));
        pk.y = bf2_to_u32(__float22bfloat162_rn(make_float2(u0.z, u0.w)));
        pk.z = bf2_to_u32(__float22bfloat162_rn(make_float2(u1.x, u1.y)));
        pk.w = bf2_to_u32(__float22bfloat162_rn(make_float2(u1.z, u1.w)));
        g_h1b[n * 32 + lane] = pk;
        // fused attn logits from fp32 accumulators
        float p[4] = {0.f,0.f,0.f,0.f}, q[4] = {0.f,0.f,0.f,0.f};
#pragma unroll
        for (int i = 0; i < 8; i++) {
            float v = acc[m][i];
            int hh = i >> 1;
            p[hh] += v * s_as[32 * i + lane];
            q[hh] += v * s_ad[32 * i + lane];
        }
#pragma unroll
        for (int off = 16; off >= 1; off >>= 1) {
#pragma unroll
            for (int hh = 0; hh < 4; hh++) {
                p[hh] += __shfl_xor_sync(0xffffffffu, p[hh], off);
                q[hh] += __shfl_xor_sync(0xffffffffu, q[hh], off);
            }
        }
        if (lane == 0) {
            g_as1[n] = make_float4(p[0], p[1], p[2], p[3]);
            g_ad1[n] = make_float4(q[0], q[1], q[2], q[3]);
        }
    }
}

// ---------------- layer 1 edge pass: warp/node, bf16 gather ----------------
__global__ void __launch_bounds__(256) edge1_kernel(const int* __restrict__ batch,
                                                    const float* __restrict__ b1) {
    __shared__ float4 s_ae[NR_];
    __shared__ float  s_b1[64];
    __shared__ float4 s_w[8][32];
    __shared__ int    s_s[8][32];
    int tid = threadIdx.x;
    if (tid < NR_) s_ae[tid] = g_ae1[tid];
    if (tid < 64) s_b1[tid] = b1[tid];
    __syncthreads();

    int warp = tid >> 5, lane = tid & 31;
    int d = blockIdx.x * 8 + warp;
    if (d >= N_) return;

    float4 ad = g_ad1[d];
    int start = g_row[d], deg = g_deg[d];

    float f[8];
#pragma unroll
    for (int i = 0; i < 8; i++) f[i] = 0.f;
    float4 dacc = make_float4(0.f,0.f,0.f,0.f);

    for (int base = 0; base < deg; base += 32) {
        int k = base + lane;
        int s = 0;
        float4 e = make_float4(0.f,0.f,0.f,0.f);
        if (k < deg) {
            int w = g_adj[start + k];
            s = w & 0xffff;
            int t = (w >> 16) & 7;
            float4 as = __ldg(&g_as1[s]);
            float4 ae = s_ae[t];
            e.x = __expf(lrelu(as.x + ad.x + ae.x));
            e.y = __expf(lrelu(as.y + ad.y + ae.y));
            e.z = __expf(lrelu(as.z + ad.z + ae.z));
            e.w = __expf(lrelu(as.w + ad.w + ae.w));
            dacc.x += e.x; dacc.y += e.y; dacc.z += e.z; dacc.w += e.w;
        }
        s_s[warp][lane] = s;
        s_w[warp][lane] = e;
        __syncwarp();
        int cnt = min(32, deg - base);
#pragma unroll 4
        for (int j = 0; j < cnt; j++) {
            float4 e2 = s_w[warp][j];
            int s2 = s_s[warp][j];
            float wgt = (lane < 8) ? e2.x : (lane < 16) ? e2.y : (lane < 24) ? e2.z : e2.w;
            uint4 hv = g_h1b[s2 * 32 + lane];   // 8 bf16: cols lane*8..+7 (head lane>>3)
            float2 a0 = __bfloat1622float2(u32_to_bf2(hv.x));
            float2 a1 = __bfloat1622float2(u32_to_bf2(hv.y));
            float2 a2 = __bfloat1622float2(u32_to_bf2(hv.z));
            float2 a3 = __bfloat1622float2(u32_to_bf2(hv.w));
            f[0] += wgt * a0.x; f[1] += wgt * a0.y;
            f[2] += wgt * a1.x; f[3] += wgt * a1.y;
            f[4] += wgt * a2.x; f[5] += wgt * a2.y;
            f[6] += wgt * a3.x; f[7] += wgt * a3.y;
        }
        __syncwarp();
    }

#pragma unroll
    for (int off = 16; off >= 1; off >>= 1) {
        dacc.x += __shfl_xor_sync(0xffffffffu, dacc.x, off);
        dacc.y += __shfl_xor_sync(0xffffffffu, dacc.y, off);
        dacc.z += __shfl_xor_sync(0xffffffffu, dacc.z, off);
        dacc.w += __shfl_xor_sync(0xffffffffu, dacc.w, off);
    }
    float denh = (lane < 8) ? dacc.x : (lane < 16) ? dacc.y : (lane < 24) ? dacc.z : dacc.w;
    float inv = 1.f / (denh + 1e-16f);
#pragma unroll
    for (int i = 0; i < 8; i++) {
        f[i] *= inv;
        f[i] += __shfl_xor_sync(0xffffffffu, f[i], 8);
        f[i] += __shfl_xor_sync(0xffffffffu, f[i], 16);
    }
    if (lane < 8) {
        float4 o0, o1;
        o0.x = eluf(0.25f * f[0] + s_b1[lane * 8 + 0]);
        o0.y = eluf(0.25f * f[1] + s_b1[lane * 8 + 1]);
        o0.z = eluf(0.25f * f[2] + s_b1[lane * 8 + 2]);
        o0.w = eluf(0.25f * f[3] + s_b1[lane * 8 + 3]);
        o1.x = eluf(0.25f * f[4] + s_b1[lane * 8 + 4]);
        o1.y = eluf(0.25f * f[5] + s_b1[lane * 8 + 5]);
        o1.z = eluf(0.25f * f[6] + s_b1[lane * 8 + 6]);
        o1.w = eluf(0.25f * f[7] + s_b1[lane * 8 + 7]);
        int g = batch[d];
        red_add_f4(&g_pool[g * 16 + lane * 2], o0);
        red_add_f4(&g_pool[g * 16 + lane * 2 + 1], o1);
        if (lane == 0) atomicAdd(&g_cnt[g], 1.0f);
    }
}

// ---------------- classifier (1 block) ----------------
__global__ void cls_kernel(const float* __restrict__ cw1, const float* __restrict__ cb1,
                           const float* __restrict__ cw2, const float* __restrict__ cb2,
                           float* __restrict__ out) {
    __shared__ float sg[4096];
    __shared__ float st[4096];
    int tid = threadIdx.x;
    for (int i = tid; i < 4096; i += 256) {
        int g = i >> 6;
        float cnt = g_cnt[g];
        sg[i] = ((float*)g_pool)[i] / fmaxf(cnt, 1.f);
    }
    __syncthreads();
    for (int i = tid; i < 4096; i += 256) {
        int g = i >> 6, k = i & 63;
        float acc = cb1[k];
        for (int c = 0; c < 64; c++) acc += sg[g * 64 + c] * cw1[c * 64 + k];
        st[i] = fmaxf(acc, 0.f);
    }
    __syncthreads();
    if (tid < 128) {
        int g = tid >> 1, o = tid & 1;
        float acc = cb2[o];
        for (int k = 0; k < 64; k++) acc += st[g * 64 + k] * cw2[k * 2 + o];
        out[tid] = acc;
    }
}

// ---------------- launch ----------------
extern "C" void kernel_launch(void* const* d_in, const int* in_sizes, int n_in,
                              void* d_out, int out_size) {
    const int*   node_type = (const int*)d_in[0];
    const int*   edge_type = (const int*)d_in[1];
    const int*   ei        = (const int*)d_in[2];
    const int*   src = ei;
    const int*   dst = ei + E_;
    const int*   batch     = (const int*)d_in[3];
    const float* node_emb  = (const float*)d_in[4];
    const float* edge_emb  = (const float*)d_in[5];
    const float* W0   = (const float*)d_in[6];
    const float* We0  = (const float*)d_in[7];
    const float* as0  = (const float*)d_in[8];
    const float* ad0  = (const float*)d_in[9];
    const float* ae0  = (const float*)d_in[10];
    const float* b0   = (const float*)d_in[11];
    const float* W1   = (const float*)d_in[12];
    const float* We1  = (const float*)d_in[13];
    const float* as1  = (const float*)d_in[14];
    const float* ad1  = (const float*)d_in[15];
    const float* ae1  = (const float*)d_in[16];
    const float* b1   = (const float*)d_in[17];
    const float* cw1  = (const float*)d_in[18];
    const float* cb1  = (const float*)d_in[19];
    const float* cw2  = (const float*)d_in[20];
    const float* cb2  = (const float*)d_in[21];
    float* out = (float*)d_out;

    cudaFuncSetAttribute(gemm_attn_kernel, cudaFuncAttributeMaxDynamicSharedMemorySize, 94208);

    zero_small<<<NBLK, 256>>>();
    hist_kernel<<<(E_ + 255) / 256, 256>>>(dst);
    scan_kernel<<<1, 1024>>>();
    scatter_kernel<<<(E_ + 255) / 256, 256>>>(src, dst, edge_type, node_type);
    prep_kernel<<<NT_ + NR_, 256>>>(node_emb, edge_emb, W0, We0, as0, ad0, ae0, We1, ae1);
    prep2_kernel<<<6, 256>>>();
    layer0_kernel<<<(N_ + 31) / 32, 1024>>>(node_type, b0);
    gemm_attn_kernel<<<(N_ + 63) / 64, 256, 94208>>>(W1, as1, ad1);
    edge1_kernel<<<(N_ + 7) / 8, 256>>>(batch, b1);
    cls_kernel<<<1, 256>>>(cw1, cb1, cw2, cb2, out);
}

// round 6
// speedup vs baseline: 1.0134x; 1.0134x over previous
#include <cuda_runtime.h>
#include <cuda_bf16.h>
#include <math.h>

#define N_    50000
#define E_    800000
#define G_    64
#define H_    4
#define C_    64
#define EDIM_ 16
#define NT_   8
#define NR_   6
#define NEG_  0.2f

#define NPAD  50176           // 1024*49
#define NBLK  196

// ---------------- scratch (device globals) ----------------
__device__ float4 g_hnt[NT_ * 64];
__device__ float4 g_asnt[NT_];
__device__ float4 g_adnt[NT_];
__device__ float4 g_ae0[NR_];
__device__ float4 g_ae1[NR_];
__device__ float  g_tab0[NT_*NT_*NR_*4];
__device__ float  g_x1f[N_ * 64];
__device__ uint4  g_h1b[N_ * 32];         // bf16 h1: [n][256 bf16] = 32 uint4/row
__device__ float4 g_as1[N_];
__device__ float4 g_ad1[N_];
__device__ float4 g_pool[1024];
__device__ float  g_cnt[64];
// CSR
__device__ int g_deg[NPAD];
__device__ int g_row[NPAD];
__device__ int g_cur[NPAD];
__device__ int g_adj[E_];                 // (ns<<19)|(etype<<16)|src

__device__ __forceinline__ float lrelu(float v) { return v > 0.f ? v : NEG_ * v; }
__device__ __forceinline__ float eluf(float v)  { return v > 0.f ? v : expm1f(v); }

__device__ __forceinline__ unsigned bf2_to_u32(__nv_bfloat162 b) {
    return *reinterpret_cast<unsigned*>(&b);
}
__device__ __forceinline__ __nv_bfloat162 u32_to_bf2(unsigned u) {
    return *reinterpret_cast<__nv_bfloat162*>(&u);
}

__device__ __forceinline__ void red_add_f4(float4* addr, float4 v) {
    asm volatile("red.global.add.v4.f32 [%0], {%1,%2,%3,%4};"
                 :: "l"(addr), "f"(v.x), "f"(v.y), "f"(v.z), "f"(v.w) : "memory");
}

// ---------------- zero small scratch ----------------
__global__ void zero_small() {
    int i = blockIdx.x * blockDim.x + threadIdx.x;
    if (i < NPAD) g_deg[i] = 0;
    if (i < 1024) g_pool[i] = make_float4(0.f, 0.f, 0.f, 0.f);
    if (i < 64)   g_cnt[i] = 0.f;
}

// ---------------- CSR build ----------------
__global__ void hist_kernel(const int* __restrict__ dst) {
    int e = blockIdx.x * blockDim.x + threadIdx.x;
    if (e < E_) atomicAdd(&g_deg[dst[e]], 1);
}

// single-block scan: 1024 threads, 49 elements each
__global__ void __launch_bounds__(1024) scan_kernel() {
    __shared__ int wsum[32];
    int t = threadIdx.x;
    int lane = t & 31, w = t >> 5;
    int base = t * 49;
    int s = 0;
#pragma unroll 7
    for (int i = 0; i < 49; i++) s += g_deg[base + i];
    int v = s;
#pragma unroll
    for (int off = 1; off < 32; off <<= 1) {
        int u = __shfl_up_sync(0xffffffffu, v, off);
        if (lane >= off) v += u;
    }
    if (lane == 31) wsum[w] = v;
    __syncthreads();
    if (w == 0) {
        int x = wsum[lane];
#pragma unroll
        for (int off = 1; off < 32; off <<= 1) {
            int u = __shfl_up_sync(0xffffffffu, x, off);
            if (lane >= off) x += u;
        }
        wsum[lane] = x;
    }
    __syncthreads();
    int off = v - s + (w > 0 ? wsum[w - 1] : 0);
#pragma unroll 7
    for (int i = 0; i < 49; i++) {
        int d = g_deg[base + i];
        g_row[base + i] = off;
        g_cur[base + i] = off;
        off += d;
    }
}

__global__ void scatter_kernel(const int* __restrict__ src, const int* __restrict__ dst,
                               const int* __restrict__ et, const int* __restrict__ ntype) {
    int e = blockIdx.x * blockDim.x + threadIdx.x;
    if (e >= E_) return;
    int d = dst[e];
    int s = src[e];
    int ns = __ldg(&ntype[s]);
    int pos = atomicAdd(&g_cur[d], 1);
    g_adj[pos] = (ns << 19) | (et[e] << 16) | s;
}

// ---------------- precompute type tables (14 blocks) ----------------
__global__ void prep_kernel(const float* __restrict__ node_emb,
                            const float* __restrict__ edge_emb,
                            const float* __restrict__ W0,
                            const float* __restrict__ We0,
                            const float* __restrict__ as0,
                            const float* __restrict__ ad0,
                            const float* __restrict__ ae0,
                            const float* __restrict__ We1,
                            const float* __restrict__ ae1) {
    int j = threadIdx.x;
    __shared__ float red_s[8];
    if (j < 8) red_s[j] = 0.f;
    __syncthreads();

    if (blockIdx.x < NT_) {
        int nt = blockIdx.x;
        float acc = 0.f;
        for (int k = 0; k < 64; k++) acc += node_emb[nt * 64 + k] * W0[k * 256 + j];
        ((float*)g_hnt)[nt * 256 + j] = acc;
        atomicAdd(&red_s[j >> 6],       acc * as0[j]);
        atomicAdd(&red_s[4 + (j >> 6)], acc * ad0[j]);
        __syncthreads();
        if (j < 4)      ((float*)g_asnt)[nt * 4 + j]       = red_s[j];
        else if (j < 8) ((float*)g_adnt)[nt * 4 + (j - 4)] = red_s[j];
    } else {
        int t = blockIdx.x - NT_;
        float h0 = 0.f, h1 = 0.f;
        for (int k = 0; k < EDIM_; k++) {
            float ev = edge_emb[t * EDIM_ + k];
            h0 += ev * We0[k * 256 + j];
            h1 += ev * We1[k * 256 + j];
        }
        atomicAdd(&red_s[j >> 6],       h0 * ae0[j]);
        atomicAdd(&red_s[4 + (j >> 6)], h1 * ae1[j]);
        __syncthreads();
        if (j < 4)      ((float*)g_ae0)[t * 4 + j]       = red_s[j];
        else if (j < 8) ((float*)g_ae1)[t * 4 + (j - 4)] = red_s[j];
    }
}

__global__ void prep2_kernel() {
    int idx = blockIdx.x * 256 + threadIdx.x;
    if (idx >= NT_*NT_*NR_*4) return;
    int h  = idx & 3;
    int r  = idx >> 2;
    int t  = r % 6;
    int r2 = r / 6;
    int ns = r2 & 7;
    int nd = r2 >> 3;
    float v = ((float*)g_asnt)[ns*4+h] + ((float*)g_adnt)[nd*4+h] + ((float*)g_ae0)[t*4+h];
    g_tab0[idx] = __expf(lrelu(v));
}

// ---------------- layer 0: warp per dst node (8 nodes/block, R3 shape) ----------------
__global__ void __launch_bounds__(256) layer0_kernel(const int* __restrict__ ntype,
                                                     const float* __restrict__ b0) {
    __shared__ float s_hnt[NT_ * 256];
    __shared__ float s_tab[NT_*NT_*NR_*4];
    __shared__ float s_b0[64];
    __shared__ int   s_cnt[8][48];
    int tid = threadIdx.x;
    for (int i = tid; i < NT_ * 256; i += 256) s_hnt[i] = ((float*)g_hnt)[i];
    for (int i = tid; i < NT_*NT_*NR_*4; i += 256) s_tab[i] = g_tab0[i];
    if (tid < 64) s_b0[tid] = b0[tid];
    __syncthreads();

    int warp = tid >> 5, lane = tid & 31;
    int d = blockIdx.x * 8 + warp;
    if (d >= N_) return;

    if (lane < 24) { s_cnt[warp][lane] = 0; s_cnt[warp][lane + 24] = 0; }
    int nd = ntype[d];
    int start = g_row[d], deg = g_deg[d];
    __syncwarp();
    for (int k = lane; k < deg; k += 32) {
        int w = g_adj[start + k];
        int t = (w >> 16) & 7;
        int ns = (w >> 19) & 7;
        atomicAdd(&s_cnt[warp][ns * 6 + t], 1);
    }
    __syncwarp();

    int ns = lane >> 2, h = lane & 3;
    float A = 0.f;
#pragma unroll
    for (int t = 0; t < 6; t++)
        A += (float)s_cnt[warp][ns * 6 + t] * s_tab[((nd * 8 + ns) * 6 + t) * 4 + h];
    float den = A;
    den += __shfl_xor_sync(0xffffffffu, den, 4);
    den += __shfl_xor_sync(0xffffffffu, den, 8);
    den += __shfl_xor_sync(0xffffffffu, den, 16);
    float ainv = A / (den + 1e-16f);

    float v0 = 0.f, v1 = 0.f;
#pragma unroll
    for (int l2 = 0; l2 < 32; l2++) {
        float a = __shfl_sync(0xffffffffu, ainv, l2);
        int base = (l2 >> 2) * 256 + (l2 & 3) * 64;
        v0 += a * s_hnt[base + lane];
        v1 += a * s_hnt[base + lane + 32];
    }
    v0 = 0.25f * v0 + s_b0[lane];
    v1 = 0.25f * v1 + s_b0[lane + 32];
    g_x1f[d * 64 + lane]      = eluf(v0);
    g_x1f[d * 64 + lane + 32] = eluf(v1);
}

// ---------------- layer 1 GEMM + fused attn logits + bf16 pack ----------------
__global__ void __launch_bounds__(256) gemm_attn_kernel(const float* __restrict__ W1,
                                                        const float* __restrict__ att_src1,
                                                        const float* __restrict__ att_dst1) {
    extern __shared__ float smem[];
    float* sW    = smem;            // 16384
    float* sx    = smem + 16384;    // 4096
    float* s_as  = smem + 20480;    // 256
    float* s_ad  = smem + 20736;    // 256
    float* strns = smem + 20992;    // 8 warps * 256
    int tid = threadIdx.x;
    int n0 = blockIdx.x * 64;
    for (int i = tid; i < 16384; i += 256) sW[i] = W1[i];
    for (int i = tid; i < 4096; i += 256) {
        int m = i >> 6, k = i & 63;
        int n = n0 + m;
        sx[i] = (n < N_) ? g_x1f[n * 64 + k] : 0.f;
    }
    if (tid < 256) { s_as[tid] = att_src1[tid]; s_ad[tid] = att_dst1[tid]; }
    __syncthreads();
    int lane = tid & 31, ng = tid >> 5;
    float* sl = strns + ng * 256;
    float acc[8][8];
#pragma unroll
    for (int m = 0; m < 8; m++)
#pragma unroll
        for (int i = 0; i < 8; i++) acc[m][i] = 0.f;
    for (int k = 0; k < 64; k++) {
        float w[8];
#pragma unroll
        for (int i = 0; i < 8; i++) w[i] = sW[k * 256 + lane + 32 * i];
#pragma unroll
        for (int m = 0; m < 8; m++) {
            float xk = sx[(ng * 8 + m) * 64 + k];
#pragma unroll
            for (int i = 0; i < 8; i++) acc[m][i] += xk * w[i];
        }
    }
#pragma unroll
    for (int m = 0; m < 8; m++) {
        int n = n0 + ng * 8 + m;
        if (n >= N_) continue;
        // transpose via smem -> bf16 pack (lane owns cols lane*8..+7)
#pragma unroll
        for (int i = 0; i < 8; i++) sl[lane + 32 * i] = acc[m][i];
        __syncwarp();
        float4 u0 = *(float4*)&sl[lane * 8];
        float4 u1 = *(float4*)&sl[lane * 8 + 4];
        __syncwarp();
        uint4 pk;
        pk.x = bf2_to_u32(__float22bfloat162_rn(make_float2(u0.x, u0.y)));
        pk.y = bf2_to_u32(__float22bfloat162_rn(make_float2(u0.z, u0.w)));
        pk.z = bf2_to_u32(__float22bfloat162_rn(make_float2(u1.x, u1.y)));
        pk.w = bf2_to_u32(__float22bfloat162_rn(make_float2(u1.z, u1.w)));
        g_h1b[n * 32 + lane] = pk;
        // fused attn logits from fp32 accumulators
        float p[4] = {0.f,0.f,0.f,0.f}, q[4] = {0.f,0.f,0.f,0.f};
#pragma unroll
        for (int i = 0; i < 8; i++) {
            float v = acc[m][i];
            int hh = i >> 1;
            p[hh] += v * s_as[32 * i + lane];
            q[hh] += v * s_ad[32 * i + lane];
        }
#pragma unroll
        for (int off = 16; off >= 1; off >>= 1) {
#pragma unroll
            for (int hh = 0; hh < 4; hh++) {
                p[hh] += __shfl_xor_sync(0xffffffffu, p[hh], off);
                q[hh] += __shfl_xor_sync(0xffffffffu, q[hh], off);
            }
        }
        if (lane == 0) {
            g_as1[n] = make_float4(p[0], p[1], p[2], p[3]);
            g_ad1[n] = make_float4(q[0], q[1], q[2], q[3]);
        }
    }
}

// ---------------- layer 1 edge pass: warp/node, bf16 gather, deep unroll ----------------
__global__ void __launch_bounds__(256) edge1_kernel(const int* __restrict__ batch,
                                                    const float* __restrict__ b1) {
    __shared__ float4 s_ae[NR_];
    __shared__ float  s_b1[64];
    __shared__ float4 s_w[8][32];
    __shared__ int    s_s[8][32];
    int tid = threadIdx.x;
    if (tid < NR_) s_ae[tid] = g_ae1[tid];
    if (tid < 64) s_b1[tid] = b1[tid];
    __syncthreads();

    int warp = tid >> 5, lane = tid & 31;
    int d = blockIdx.x * 8 + warp;
    if (d >= N_) return;

    float4 ad = g_ad1[d];
    int start = g_row[d], deg = g_deg[d];

    float f[8];
#pragma unroll
    for (int i = 0; i < 8; i++) f[i] = 0.f;
    float4 dacc = make_float4(0.f,0.f,0.f,0.f);

    for (int base = 0; base < deg; base += 32) {
        int k = base + lane;
        int s = 0;
        float4 e = make_float4(0.f,0.f,0.f,0.f);
        if (k < deg) {
            int w = g_adj[start + k];
            s = w & 0xffff;
            int t = (w >> 16) & 7;
            float4 as = __ldg(&g_as1[s]);
            float4 ae = s_ae[t];
            e.x = __expf(lrelu(as.x + ad.x + ae.x));
            e.y = __expf(lrelu(as.y + ad.y + ae.y));
            e.z = __expf(lrelu(as.z + ad.z + ae.z));
            e.w = __expf(lrelu(as.w + ad.w + ae.w));
            dacc.x += e.x; dacc.y += e.y; dacc.z += e.z; dacc.w += e.w;
        }
        s_s[warp][lane] = s;
        s_w[warp][lane] = e;
        __syncwarp();
        int cnt = min(32, deg - base);
#pragma unroll 8
        for (int j = 0; j < cnt; j++) {
            float4 e2 = s_w[warp][j];
            int s2 = s_s[warp][j];
            float wgt = (lane < 8) ? e2.x : (lane < 16) ? e2.y : (lane < 24) ? e2.z : e2.w;
            uint4 hv = g_h1b[s2 * 32 + lane];   // 8 bf16: cols lane*8..+7 (head lane>>3)
            float2 a0 = __bfloat1622float2(u32_to_bf2(hv.x));
            float2 a1 = __bfloat1622float2(u32_to_bf2(hv.y));
            float2 a2 = __bfloat1622float2(u32_to_bf2(hv.z));
            float2 a3 = __bfloat1622float2(u32_to_bf2(hv.w));
            f[0] += wgt * a0.x; f[1] += wgt * a0.y;
            f[2] += wgt * a1.x; f[3] += wgt * a1.y;
            f[4] += wgt * a2.x; f[5] += wgt * a2.y;
            f[6] += wgt * a3.x; f[7] += wgt * a3.y;
        }
        __syncwarp();
    }

#pragma unroll
    for (int off = 16; off >= 1; off >>= 1) {
        dacc.x += __shfl_xor_sync(0xffffffffu, dacc.x, off);
        dacc.y += __shfl_xor_sync(0xffffffffu, dacc.y, off);
        dacc.z += __shfl_xor_sync(0xffffffffu, dacc.z, off);
        dacc.w += __shfl_xor_sync(0xffffffffu, dacc.w, off);
    }
    float denh = (lane < 8) ? dacc.x : (lane < 16) ? dacc.y : (lane < 24) ? dacc.z : dacc.w;
    float inv = 1.f / (denh + 1e-16f);
#pragma unroll
    for (int i = 0; i < 8; i++) {
        f[i] *= inv;
        f[i] += __shfl_xor_sync(0xffffffffu, f[i], 8);
        f[i] += __shfl_xor_sync(0xffffffffu, f[i], 16);
    }
    if (lane < 8) {
        float4 o0, o1;
        o0.x = eluf(0.25f * f[0] + s_b1[lane * 8 + 0]);
        o0.y = eluf(0.25f * f[1] + s_b1[lane * 8 + 1]);
        o0.z = eluf(0.25f * f[2] + s_b1[lane * 8 + 2]);
        o0.w = eluf(0.25f * f[3] + s_b1[lane * 8 + 3]);
        o1.x = eluf(0.25f * f[4] + s_b1[lane * 8 + 4]);
        o1.y = eluf(0.25f * f[5] + s_b1[lane * 8 + 5]);
        o1.z = eluf(0.25f * f[6] + s_b1[lane * 8 + 6]);
        o1.w = eluf(0.25f * f[7] + s_b1[lane * 8 + 7]);
        int g = batch[d];
        red_add_f4(&g_pool[g * 16 + lane * 2], o0);
        red_add_f4(&g_pool[g * 16 + lane * 2 + 1], o1);
        if (lane == 0) atomicAdd(&g_cnt[g], 1.0f);
    }
}

// ---------------- classifier (1 block) ----------------
__global__ void cls_kernel(const float* __restrict__ cw1, const float* __restrict__ cb1,
                           const float* __restrict__ cw2, const float* __restrict__ cb2,
                           float* __restrict__ out) {
    __shared__ float sg[4096];
    __shared__ float st[4096];
    int tid = threadIdx.x;
    for (int i = tid; i < 4096; i += 256) {
        int g = i >> 6;
        float cnt = g_cnt[g];
        sg[i] = ((float*)g_pool)[i] / fmaxf(cnt, 1.f);
    }
    __syncthreads();
    for (int i = tid; i < 4096; i += 256) {
        int g = i >> 6, k = i & 63;
        float acc = cb1[k];
        for (int c = 0; c < 64; c++) acc += sg[g * 64 + c] * cw1[c * 64 + k];
        st[i] = fmaxf(acc, 0.f);
    }
    __syncthreads();
    if (tid < 128) {
        int g = tid >> 1, o = tid & 1;
        float acc = cb2[o];
        for (int k = 0; k < 64; k++) acc += st[g * 64 + k] * cw2[k * 2 + o];
        out[tid] = acc;
    }
}

// ---------------- launch ----------------
extern "C" void kernel_launch(void* const* d_in, const int* in_sizes, int n_in,
                              void* d_out, int out_size) {
    const int*   node_type = (const int*)d_in[0];
    const int*   edge_type = (const int*)d_in[1];
    const int*   ei        = (const int*)d_in[2];
    const int*   src = ei;
    const int*   dst = ei + E_;
    const int*   batch     = (const int*)d_in[3];
    const float* node_emb  = (const float*)d_in[4];
    const float* edge_emb  = (const float*)d_in[5];
    const float* W0   = (const float*)d_in[6];
    const float* We0  = (const float*)d_in[7];
    const float* as0  = (const float*)d_in[8];
    const float* ad0  = (const float*)d_in[9];
    const float* ae0  = (const float*)d_in[10];
    const float* b0   = (const float*)d_in[11];
    const float* W1   = (const float*)d_in[12];
    const float* We1  = (const float*)d_in[13];
    const float* as1  = (const float*)d_in[14];
    const float* ad1  = (const float*)d_in[15];
    const float* ae1  = (const float*)d_in[16];
    const float* b1   = (const float*)d_in[17];
    const float* cw1  = (const float*)d_in[18];
    const float* cb1  = (const float*)d_in[19];
    const float* cw2  = (const float*)d_in[20];
    const float* cb2  = (const float*)d_in[21];
    float* out = (float*)d_out;

    cudaFuncSetAttribute(gemm_attn_kernel, cudaFuncAttributeMaxDynamicSharedMemorySize, 94208);

    zero_small<<<NBLK, 256>>>();
    hist_kernel<<<(E_ + 255) / 256, 256>>>(dst);
    scan_kernel<<<1, 1024>>>();
    scatter_kernel<<<(E_ + 255) / 256, 256>>>(src, dst, edge_type, node_type);
    prep_kernel<<<NT_ + NR_, 256>>>(node_emb, edge_emb, W0, We0, as0, ad0, ae0, We1, ae1);
    prep2_kernel<<<6, 256>>>();
    layer0_kernel<<<(N_ + 7) / 8, 256>>>(node_type, b0);
    gemm_attn_kernel<<<(N_ + 63) / 64, 256, 94208>>>(W1, as1, ad1);
    edge1_kernel<<<(N_ + 7) / 8, 256>>>(batch, b1);
    cls_kernel<<<1, 256>>>(cw1, cb1, cw2, cb2, out);
}

// round 7
// speedup vs baseline: 1.0195x; 1.0060x over previous
#include <cuda_runtime.h>
#include <cuda_bf16.h>
#include <math.h>

#define N_    50000
#define E_    800000
#define G_    64
#define H_    4
#define C_    64
#define EDIM_ 16
#define NT_   8
#define NR_   6
#define NEG_  0.2f

#define NPAD  50176           // 1024*49
#define NBLK  196

// ---------------- scratch (device globals) ----------------
__device__ float4 g_hnt[NT_ * 64];
__device__ float4 g_asnt[NT_];
__device__ float4 g_adnt[NT_];
__device__ float4 g_ae0[NR_];
__device__ float4 g_ae1[NR_];
__device__ float  g_tab0[NT_*NT_*NR_*4];
__device__ float  g_x1f[N_ * 64];
__device__ uint4  g_h1b[N_ * 32];         // bf16 h1: [n][256 bf16] = 32 uint4/row
__device__ float4 g_as1[N_];
__device__ float4 g_ad1[N_];
__device__ float4 g_pool[1024];
__device__ float  g_cnt[64];
// CSR
__device__ int g_deg[NPAD];
__device__ int g_row[NPAD];
__device__ int g_cur[NPAD];
__device__ int g_adj[E_];                 // (ns<<19)|(etype<<16)|src

__device__ __forceinline__ float lrelu(float v) { return v > 0.f ? v : NEG_ * v; }
__device__ __forceinline__ float eluf(float v)  { return v > 0.f ? v : expm1f(v); }

__device__ __forceinline__ unsigned bf2_to_u32(__nv_bfloat162 b) {
    return *reinterpret_cast<unsigned*>(&b);
}
// bf16x2 -> two f32 via pure ALU ops (bf16 == top 16 bits of f32)
__device__ __forceinline__ float bf_lo(unsigned u) { return __uint_as_float(u << 16); }
__device__ __forceinline__ float bf_hi(unsigned u) { return __uint_as_float(u & 0xffff0000u); }

__device__ __forceinline__ void red_add_f4(float4* addr, float4 v) {
    asm volatile("red.global.add.v4.f32 [%0], {%1,%2,%3,%4};"
                 :: "l"(addr), "f"(v.x), "f"(v.y), "f"(v.z), "f"(v.w) : "memory");
}

// ---------------- zero small scratch ----------------
__global__ void zero_small() {
    int i = blockIdx.x * blockDim.x + threadIdx.x;
    if (i < NPAD) g_deg[i] = 0;
    if (i < 1024) g_pool[i] = make_float4(0.f, 0.f, 0.f, 0.f);
    if (i < 64)   g_cnt[i] = 0.f;
}

// ---------------- CSR build ----------------
__global__ void hist_kernel(const int* __restrict__ dst) {
    int e = blockIdx.x * blockDim.x + threadIdx.x;
    if (e < E_) atomicAdd(&g_deg[dst[e]], 1);
}

// single-block scan: 1024 threads, 49 elements each
__global__ void __launch_bounds__(1024) scan_kernel() {
    __shared__ int wsum[32];
    int t = threadIdx.x;
    int lane = t & 31, w = t >> 5;
    int base = t * 49;
    int s = 0;
#pragma unroll 7
    for (int i = 0; i < 49; i++) s += g_deg[base + i];
    int v = s;
#pragma unroll
    for (int off = 1; off < 32; off <<= 1) {
        int u = __shfl_up_sync(0xffffffffu, v, off);
        if (lane >= off) v += u;
    }
    if (lane == 31) wsum[w] = v;
    __syncthreads();
    if (w == 0) {
        int x = wsum[lane];
#pragma unroll
        for (int off = 1; off < 32; off <<= 1) {
            int u = __shfl_up_sync(0xffffffffu, x, off);
            if (lane >= off) x += u;
        }
        wsum[lane] = x;
    }
    __syncthreads();
    int off = v - s + (w > 0 ? wsum[w - 1] : 0);
#pragma unroll 7
    for (int i = 0; i < 49; i++) {
        int d = g_deg[base + i];
        g_row[base + i] = off;
        g_cur[base + i] = off;
        off += d;
    }
}

__global__ void scatter_kernel(const int* __restrict__ src, const int* __restrict__ dst,
                               const int* __restrict__ et, const int* __restrict__ ntype) {
    int e = blockIdx.x * blockDim.x + threadIdx.x;
    if (e >= E_) return;
    int d = dst[e];
    int s = src[e];
    int ns = __ldg(&ntype[s]);
    int pos = atomicAdd(&g_cur[d], 1);
    g_adj[pos] = (ns << 19) | (et[e] << 16) | s;
}

// ---------------- precompute type tables (14 blocks) ----------------
__global__ void prep_kernel(const float* __restrict__ node_emb,
                            const float* __restrict__ edge_emb,
                            const float* __restrict__ W0,
                            const float* __restrict__ We0,
                            const float* __restrict__ as0,
                            const float* __restrict__ ad0,
                            const float* __restrict__ ae0,
                            const float* __restrict__ We1,
                            const float* __restrict__ ae1) {
    int j = threadIdx.x;
    __shared__ float red_s[8];
    if (j < 8) red_s[j] = 0.f;
    __syncthreads();

    if (blockIdx.x < NT_) {
        int nt = blockIdx.x;
        float acc = 0.f;
        for (int k = 0; k < 64; k++) acc += node_emb[nt * 64 + k] * W0[k * 256 + j];
        ((float*)g_hnt)[nt * 256 + j] = acc;
        atomicAdd(&red_s[j >> 6],       acc * as0[j]);
        atomicAdd(&red_s[4 + (j >> 6)], acc * ad0[j]);
        __syncthreads();
        if (j < 4)      ((float*)g_asnt)[nt * 4 + j]       = red_s[j];
        else if (j < 8) ((float*)g_adnt)[nt * 4 + (j - 4)] = red_s[j];
    } else {
        int t = blockIdx.x - NT_;
        float h0 = 0.f, h1 = 0.f;
        for (int k = 0; k < EDIM_; k++) {
            float ev = edge_emb[t * EDIM_ + k];
            h0 += ev * We0[k * 256 + j];
            h1 += ev * We1[k * 256 + j];
        }
        atomicAdd(&red_s[j >> 6],       h0 * ae0[j]);
        atomicAdd(&red_s[4 + (j >> 6)], h1 * ae1[j]);
        __syncthreads();
        if (j < 4)      ((float*)g_ae0)[t * 4 + j]       = red_s[j];
        else if (j < 8) ((float*)g_ae1)[t * 4 + (j - 4)] = red_s[j];
    }
}

__global__ void prep2_kernel() {
    int idx = blockIdx.x * 256 + threadIdx.x;
    if (idx >= NT_*NT_*NR_*4) return;
    int h  = idx & 3;
    int r  = idx >> 2;
    int t  = r % 6;
    int r2 = r / 6;
    int ns = r2 & 7;
    int nd = r2 >> 3;
    float v = ((float*)g_asnt)[ns*4+h] + ((float*)g_adnt)[nd*4+h] + ((float*)g_ae0)[t*4+h];
    g_tab0[idx] = __expf(lrelu(v));
}

// ---------------- layer 0: warp per dst node (8 nodes/block) ----------------
__global__ void __launch_bounds__(256) layer0_kernel(const int* __restrict__ ntype,
                                                     const float* __restrict__ b0) {
    __shared__ float s_hnt[NT_ * 256];
    __shared__ float s_tab[NT_*NT_*NR_*4];
    __shared__ float s_b0[64];
    __shared__ int   s_cnt[8][48];
    int tid = threadIdx.x;
    for (int i = tid; i < NT_ * 256; i += 256) s_hnt[i] = ((float*)g_hnt)[i];
    for (int i = tid; i < NT_*NT_*NR_*4; i += 256) s_tab[i] = g_tab0[i];
    if (tid < 64) s_b0[tid] = b0[tid];
    __syncthreads();

    int warp = tid >> 5, lane = tid & 31;
    int d = blockIdx.x * 8 + warp;
    if (d >= N_) return;

    if (lane < 24) { s_cnt[warp][lane] = 0; s_cnt[warp][lane + 24] = 0; }
    int nd = ntype[d];
    int start = g_row[d], deg = g_deg[d];
    __syncwarp();
    for (int k = lane; k < deg; k += 32) {
        int w = g_adj[start + k];
        int t = (w >> 16) & 7;
        int ns = (w >> 19) & 7;
        atomicAdd(&s_cnt[warp][ns * 6 + t], 1);
    }
    __syncwarp();

    int ns = lane >> 2, h = lane & 3;
    float A = 0.f;
#pragma unroll
    for (int t = 0; t < 6; t++)
        A += (float)s_cnt[warp][ns * 6 + t] * s_tab[((nd * 8 + ns) * 6 + t) * 4 + h];
    float den = A;
    den += __shfl_xor_sync(0xffffffffu, den, 4);
    den += __shfl_xor_sync(0xffffffffu, den, 8);
    den += __shfl_xor_sync(0xffffffffu, den, 16);
    float ainv = A / (den + 1e-16f);

    float v0 = 0.f, v1 = 0.f;
#pragma unroll
    for (int l2 = 0; l2 < 32; l2++) {
        float a = __shfl_sync(0xffffffffu, ainv, l2);
        int base = (l2 >> 2) * 256 + (l2 & 3) * 64;
        v0 += a * s_hnt[base + lane];
        v1 += a * s_hnt[base + lane + 32];
    }
    v0 = 0.25f * v0 + s_b0[lane];
    v1 = 0.25f * v1 + s_b0[lane + 32];
    g_x1f[d * 64 + lane]      = eluf(v0);
    g_x1f[d * 64 + lane + 32] = eluf(v1);
}

// ---------------- layer 1 GEMM + fused attn logits + bf16 pack ----------------
__global__ void __launch_bounds__(256) gemm_attn_kernel(const float* __restrict__ W1,
                                                        const float* __restrict__ att_src1,
                                                        const float* __restrict__ att_dst1) {
    extern __shared__ float smem[];
    float* sW    = smem;            // 16384
    float* sx    = smem + 16384;    // 4096
    float* s_as  = smem + 20480;    // 256
    float* s_ad  = smem + 20736;    // 256
    float* strns = smem + 20992;    // 8 warps * 256
    int tid = threadIdx.x;
    int n0 = blockIdx.x * 64;
    for (int i = tid; i < 16384; i += 256) sW[i] = W1[i];
    for (int i = tid; i < 4096; i += 256) {
        int m = i >> 6, k = i & 63;
        int n = n0 + m;
        sx[i] = (n < N_) ? g_x1f[n * 64 + k] : 0.f;
    }
    if (tid < 256) { s_as[tid] = att_src1[tid]; s_ad[tid] = att_dst1[tid]; }
    __syncthreads();
    int lane = tid & 31, ng = tid >> 5;
    float* sl = strns + ng * 256;
    float acc[8][8];
#pragma unroll
    for (int m = 0; m < 8; m++)
#pragma unroll
        for (int i = 0; i < 8; i++) acc[m][i] = 0.f;
    for (int k = 0; k < 64; k++) {
        float w[8];
#pragma unroll
        for (int i = 0; i < 8; i++) w[i] = sW[k * 256 + lane + 32 * i];
#pragma unroll
        for (int m = 0; m < 8; m++) {
            float xk = sx[(ng * 8 + m) * 64 + k];
#pragma unroll
            for (int i = 0; i < 8; i++) acc[m][i] += xk * w[i];
        }
    }
#pragma unroll
    for (int m = 0; m < 8; m++) {
        int n = n0 + ng * 8 + m;
        if (n >= N_) continue;
        // transpose via smem -> bf16 pack (lane owns cols lane*8..+7)
#pragma unroll
        for (int i = 0; i < 8; i++) sl[lane + 32 * i] = acc[m][i];
        __syncwarp();
        float4 u0 = *(float4*)&sl[lane * 8];
        float4 u1 = *(float4*)&sl[lane * 8 + 4];
        __syncwarp();
        uint4 pk;
        pk.x = bf2_to_u32(__float22bfloat162_rn(make_float2(u0.x, u0.y)));
        pk.y = bf2_to_u32(__float22bfloat162_rn(make_float2(u0.z, u0.w)));
        pk.z = bf2_to_u32(__float22bfloat162_rn(make_float2(u1.x, u1.y)));
        pk.w = bf2_to_u32(__float22bfloat162_rn(make_float2(u1.z, u1.w)));
        g_h1b[n * 32 + lane] = pk;
        // fused attn logits from fp32 accumulators
        float p[4] = {0.f,0.f,0.f,0.f}, q[4] = {0.f,0.f,0.f,0.f};
#pragma unroll
        for (int i = 0; i < 8; i++) {
            float v = acc[m][i];
            int hh = i >> 1;
            p[hh] += v * s_as[32 * i + lane];
            q[hh] += v * s_ad[32 * i + lane];
        }
#pragma unroll
        for (int off = 16; off >= 1; off >>= 1) {
#pragma unroll
            for (int hh = 0; hh < 4; hh++) {
                p[hh] += __shfl_xor_sync(0xffffffffu, p[hh], off);
                q[hh] += __shfl_xor_sync(0xffffffffu, q[hh], off);
            }
        }
        if (lane == 0) {
            g_as1[n] = make_float4(p[0], p[1], p[2], p[3]);
            g_ad1[n] = make_float4(q[0], q[1], q[2], q[3]);
        }
    }
}

// ---------------- layer 1 edge pass: warp/node, bf16 gather, ALU-only cvt ----------------
__global__ void __launch_bounds__(256) edge1_kernel(const int* __restrict__ batch,
                                                    const float* __restrict__ b1) {
    __shared__ float4 s_ae[NR_];
    __shared__ float  s_b1[64];
    __shared__ float4 s_w[8][32];
    __shared__ int    s_s[8][32];
    int tid = threadIdx.x;
    if (tid < NR_) s_ae[tid] = g_ae1[tid];
    if (tid < 64) s_b1[tid] = b1[tid];
    __syncthreads();

    int warp = tid >> 5, lane = tid & 31;
    int d = blockIdx.x * 8 + warp;
    if (d >= N_) return;

    float4 ad = g_ad1[d];
    int start = g_row[d], deg = g_deg[d];

    float f[8];
#pragma unroll
    for (int i = 0; i < 8; i++) f[i] = 0.f;
    float4 dacc = make_float4(0.f,0.f,0.f,0.f);

    for (int base = 0; base < deg; base += 32) {
        int k = base + lane;
        int s = 0;
        float4 e = make_float4(0.f,0.f,0.f,0.f);
        if (k < deg) {
            int w = g_adj[start + k];
            s = w & 0xffff;
            int t = (w >> 16) & 7;
            float4 as = __ldg(&g_as1[s]);
            float4 ae = s_ae[t];
            e.x = __expf(lrelu(as.x + ad.x + ae.x));
            e.y = __expf(lrelu(as.y + ad.y + ae.y));
            e.z = __expf(lrelu(as.z + ad.z + ae.z));
            e.w = __expf(lrelu(as.w + ad.w + ae.w));
            dacc.x += e.x; dacc.y += e.y; dacc.z += e.z; dacc.w += e.w;
        }
        s_s[warp][lane] = s;
        s_w[warp][lane] = e;
        __syncwarp();
        int cnt = min(32, deg - base);
#pragma unroll 8
        for (int j = 0; j < cnt; j++) {
            float4 e2 = s_w[warp][j];
            int s2 = s_s[warp][j];
            float wgt = (lane < 8) ? e2.x : (lane < 16) ? e2.y : (lane < 24) ? e2.z : e2.w;
            uint4 hv = g_h1b[s2 * 32 + lane];   // 8 bf16: cols lane*8..+7 (head lane>>3)
            f[0] += wgt * bf_lo(hv.x); f[1] += wgt * bf_hi(hv.x);
            f[2] += wgt * bf_lo(hv.y); f[3] += wgt * bf_hi(hv.y);
            f[4] += wgt * bf_lo(hv.z); f[5] += wgt * bf_hi(hv.z);
            f[6] += wgt * bf_lo(hv.w); f[7] += wgt * bf_hi(hv.w);
        }
        __syncwarp();
    }

#pragma unroll
    for (int off = 16; off >= 1; off >>= 1) {
        dacc.x += __shfl_xor_sync(0xffffffffu, dacc.x, off);
        dacc.y += __shfl_xor_sync(0xffffffffu, dacc.y, off);
        dacc.z += __shfl_xor_sync(0xffffffffu, dacc.z, off);
        dacc.w += __shfl_xor_sync(0xffffffffu, dacc.w, off);
    }
    float denh = (lane < 8) ? dacc.x : (lane < 16) ? dacc.y : (lane < 24) ? dacc.z : dacc.w;
    float inv = 1.f / (denh + 1e-16f);
#pragma unroll
    for (int i = 0; i < 8; i++) {
        f[i] *= inv;
        f[i] += __shfl_xor_sync(0xffffffffu, f[i], 8);
        f[i] += __shfl_xor_sync(0xffffffffu, f[i], 16);
    }
    if (lane < 8) {
        float4 o0, o1;
        o0.x = eluf(0.25f * f[0] + s_b1[lane * 8 + 0]);
        o0.y = eluf(0.25f * f[1] + s_b1[lane * 8 + 1]);
        o0.z = eluf(0.25f * f[2] + s_b1[lane * 8 + 2]);
        o0.w = eluf(0.25f * f[3] + s_b1[lane * 8 + 3]);
        o1.x = eluf(0.25f * f[4] + s_b1[lane * 8 + 4]);
        o1.y = eluf(0.25f * f[5] + s_b1[lane * 8 + 5]);
        o1.z = eluf(0.25f * f[6] + s_b1[lane * 8 + 6]);
        o1.w = eluf(0.25f * f[7] + s_b1[lane * 8 + 7]);
        int g = batch[d];
        red_add_f4(&g_pool[g * 16 + lane * 2], o0);
        red_add_f4(&g_pool[g * 16 + lane * 2 + 1], o1);
        if (lane == 0) atomicAdd(&g_cnt[g], 1.0f);
    }
}

// ---------------- classifier (1 block) ----------------
__global__ void cls_kernel(const float* __restrict__ cw1, const float* __restrict__ cb1,
                           const float* __restrict__ cw2, const float* __restrict__ cb2,
                           float* __restrict__ out) {
    __shared__ float sg[4096];
    __shared__ float st[4096];
    int tid = threadIdx.x;
    for (int i = tid; i < 4096; i += 256) {
        int g = i >> 6;
        float cnt = g_cnt[g];
        sg[i] = ((float*)g_pool)[i] / fmaxf(cnt, 1.f);
    }
    __syncthreads();
    for (int i = tid; i < 4096; i += 256) {
        int g = i >> 6, k = i & 63;
        float acc = cb1[k];
        for (int c = 0; c < 64; c++) acc += sg[g * 64 + c] * cw1[c * 64 + k];
        st[i] = fmaxf(acc, 0.f);
    }
    __syncthreads();
    if (tid < 128) {
        int g = tid >> 1, o = tid & 1;
        float acc = cb2[o];
        for (int k = 0; k < 64; k++) acc += st[g * 64 + k] * cw2[k * 2 + o];
        out[tid] = acc;
    }
}

// ---------------- launch ----------------
extern "C" void kernel_launch(void* const* d_in, const int* in_sizes, int n_in,
                              void* d_out, int out_size) {
    const int*   node_type = (const int*)d_in[0];
    const int*   edge_type = (const int*)d_in[1];
    const int*   ei        = (const int*)d_in[2];
    const int*   src = ei;
    const int*   dst = ei + E_;
    const int*   batch     = (const int*)d_in[3];
    const float* node_emb  = (const float*)d_in[4];
    const float* edge_emb  = (const float*)d_in[5];
    const float* W0   = (const float*)d_in[6];
    const float* We0  = (const float*)d_in[7];
    const float* as0  = (const float*)d_in[8];
    const float* ad0  = (const float*)d_in[9];
    const float* ae0  = (const float*)d_in[10];
    const float* b0   = (const float*)d_in[11];
    const float* W1   = (const float*)d_in[12];
    const float* We1  = (const float*)d_in[13];
    const float* as1  = (const float*)d_in[14];
    const float* ad1  = (const float*)d_in[15];
    const float* ae1  = (const float*)d_in[16];
    const float* b1   = (const float*)d_in[17];
    const float* cw1  = (const float*)d_in[18];
    const float* cb1  = (const float*)d_in[19];
    const float* cw2  = (const float*)d_in[20];
    const float* cb2  = (const float*)d_in[21];
    float* out = (float*)d_out;

    cudaFuncSetAttribute(gemm_attn_kernel, cudaFuncAttributeMaxDynamicSharedMemorySize, 94208);

    zero_small<<<NBLK, 256>>>();
    hist_kernel<<<(E_ + 255) / 256, 256>>>(dst);
    scan_kernel<<<1, 1024>>>();
    scatter_kernel<<<(E_ + 255) / 256, 256>>>(src, dst, edge_type, node_type);
    prep_kernel<<<NT_ + NR_, 256>>>(node_emb, edge_emb, W0, We0, as0, ad0, ae0, We1, ae1);
    prep2_kernel<<<6, 256>>>();
    layer0_kernel<<<(N_ + 7) / 8, 256>>>(node_type, b0);
    gemm_attn_kernel<<<(N_ + 63) / 64, 256, 94208>>>(W1, as1, ad1);
    edge1_kernel<<<(N_ + 7) / 8, 256>>>(batch, b1);
    cls_kernel<<<1, 256>>>(cw1, cb1, cw2, cb2, out);
}

// round 8
// speedup vs baseline: 1.2743x; 1.2499x over previous
#include <cuda_runtime.h>
#include <cuda_bf16.h>
#include <math.h>

#define N_    50000
#define E_    800000
#define G_    64
#define H_    4
#define C_    64
#define EDIM_ 16
#define NT_   8
#define NR_   6
#define NEG_  0.2f

#define NPAD  50176           // 196*256
#define NBLK  196

// ---------------- scratch (device globals) ----------------
__device__ float4 g_hnt[NT_ * 64];
__device__ float4 g_asnt[NT_];
__device__ float4 g_adnt[NT_];
__device__ float4 g_ae0[NR_];
__device__ float4 g_ae1[NR_];
__device__ float  g_tab0[NT_*NT_*NR_*4];
__device__ float  g_x1f[N_ * 64];
__device__ uint4  g_h1b[N_ * 32];         // bf16 h1: [n][256 bf16] = 32 uint4/row
__device__ float4 g_as1[N_];
__device__ float4 g_ad1[N_];
__device__ float4 g_pool[1024];
__device__ float  g_cnt[64];
// CSR
__device__ int g_deg[NPAD];
__device__ int g_row[NPAD];
__device__ int g_cur[NPAD];
__device__ int g_bsum[256];
__device__ int g_boff[256];
__device__ int g_adj[E_];                 // (ns<<19)|(etype<<16)|src

__device__ __forceinline__ float lrelu(float v) { return v > 0.f ? v : NEG_ * v; }
__device__ __forceinline__ float eluf(float v)  { return v > 0.f ? v : expm1f(v); }

__device__ __forceinline__ unsigned bf2_to_u32(__nv_bfloat162 b) {
    return *reinterpret_cast<unsigned*>(&b);
}
// bf16x2 -> two f32 via pure ALU ops (bf16 == top 16 bits of f32)
__device__ __forceinline__ float bf_lo(unsigned u) { return __uint_as_float(u << 16); }
__device__ __forceinline__ float bf_hi(unsigned u) { return __uint_as_float(u & 0xffff0000u); }

__device__ __forceinline__ void red_add_f4(float4* addr, float4 v) {
    asm volatile("red.global.add.v4.f32 [%0], {%1,%2,%3,%4};"
                 :: "l"(addr), "f"(v.x), "f"(v.y), "f"(v.z), "f"(v.w) : "memory");
}

// ---------------- zero small scratch ----------------
__global__ void zero_small() {
    int i = blockIdx.x * blockDim.x + threadIdx.x;
    if (i < NPAD) g_deg[i] = 0;
    if (i < 1024) g_pool[i] = make_float4(0.f, 0.f, 0.f, 0.f);
    if (i < 64)   g_cnt[i] = 0.f;
    if (i < 256)  { g_bsum[i] = 0; g_boff[i] = 0; }
}

// ---------------- CSR build (coalesced 3-phase scan, R3 shape) ----------------
__global__ void hist_kernel(const int* __restrict__ dst) {
    int e = blockIdx.x * blockDim.x + threadIdx.x;
    if (e < E_) atomicAdd(&g_deg[dst[e]], 1);
}

__global__ void scanA_kernel() {
    __shared__ int sh[256];
    int i = blockIdx.x * 256 + threadIdx.x;
    int v = g_deg[i];
    sh[threadIdx.x] = v;
    __syncthreads();
#pragma unroll
    for (int off = 1; off < 256; off <<= 1) {
        int t = (threadIdx.x >= off) ? sh[threadIdx.x - off] : 0;
        __syncthreads();
        sh[threadIdx.x] += t;
        __syncthreads();
    }
    g_row[i] = sh[threadIdx.x] - v;
    if (threadIdx.x == 255) g_bsum[blockIdx.x] = sh[255];
}

__global__ void scanB_kernel() {
    __shared__ int sh[256];
    int t = threadIdx.x;
    int v = g_bsum[t];
    sh[t] = v;
    __syncthreads();
#pragma unroll
    for (int off = 1; off < 256; off <<= 1) {
        int u = (t >= off) ? sh[t - off] : 0;
        __syncthreads();
        sh[t] += u;
        __syncthreads();
    }
    g_boff[t] = sh[t] - v;
}

__global__ void scanC_kernel() {
    int i = blockIdx.x * 256 + threadIdx.x;
    int r = g_row[i] + g_boff[blockIdx.x];
    g_row[i] = r;
    g_cur[i] = r;
}

__global__ void scatter_kernel(const int* __restrict__ src, const int* __restrict__ dst,
                               const int* __restrict__ et, const int* __restrict__ ntype) {
    int e = blockIdx.x * blockDim.x + threadIdx.x;
    if (e >= E_) return;
    int d = dst[e];
    int s = src[e];
    int ns = __ldg(&ntype[s]);
    int pos = atomicAdd(&g_cur[d], 1);
    g_adj[pos] = (ns << 19) | (et[e] << 16) | s;
}

// ---------------- precompute type tables (14 blocks) ----------------
__global__ void prep_kernel(const float* __restrict__ node_emb,
                            const float* __restrict__ edge_emb,
                            const float* __restrict__ W0,
                            const float* __restrict__ We0,
                            const float* __restrict__ as0,
                            const float* __restrict__ ad0,
                            const float* __restrict__ ae0,
                            const float* __restrict__ We1,
                            const float* __restrict__ ae1) {
    int j = threadIdx.x;
    __shared__ float red_s[8];
    if (j < 8) red_s[j] = 0.f;
    __syncthreads();

    if (blockIdx.x < NT_) {
        int nt = blockIdx.x;
        float acc = 0.f;
        for (int k = 0; k < 64; k++) acc += node_emb[nt * 64 + k] * W0[k * 256 + j];
        ((float*)g_hnt)[nt * 256 + j] = acc;
        atomicAdd(&red_s[j >> 6],       acc * as0[j]);
        atomicAdd(&red_s[4 + (j >> 6)], acc * ad0[j]);
        __syncthreads();
        if (j < 4)      ((float*)g_asnt)[nt * 4 + j]       = red_s[j];
        else if (j < 8) ((float*)g_adnt)[nt * 4 + (j - 4)] = red_s[j];
    } else {
        int t = blockIdx.x - NT_;
        float h0 = 0.f, h1 = 0.f;
        for (int k = 0; k < EDIM_; k++) {
            float ev = edge_emb[t * EDIM_ + k];
            h0 += ev * We0[k * 256 + j];
            h1 += ev * We1[k * 256 + j];
        }
        atomicAdd(&red_s[j >> 6],       h0 * ae0[j]);
        atomicAdd(&red_s[4 + (j >> 6)], h1 * ae1[j]);
        __syncthreads();
        if (j < 4)      ((float*)g_ae0)[t * 4 + j]       = red_s[j];
        else if (j < 8) ((float*)g_ae1)[t * 4 + (j - 4)] = red_s[j];
    }
}

__global__ void prep2_kernel() {
    int idx = blockIdx.x * 256 + threadIdx.x;
    if (idx >= NT_*NT_*NR_*4) return;
    int h  = idx & 3;
    int r  = idx >> 2;
    int t  = r % 6;
    int r2 = r / 6;
    int ns = r2 & 7;
    int nd = r2 >> 3;
    float v = ((float*)g_asnt)[ns*4+h] + ((float*)g_adnt)[nd*4+h] + ((float*)g_ae0)[t*4+h];
    g_tab0[idx] = __expf(lrelu(v));
}

// ---------------- layer 0: warp per dst node (8 nodes/block) ----------------
__global__ void __launch_bounds__(256) layer0_kernel(const int* __restrict__ ntype,
                                                     const float* __restrict__ b0) {
    __shared__ float s_hnt[NT_ * 256];
    __shared__ float s_tab[NT_*NT_*NR_*4];
    __shared__ float s_b0[64];
    __shared__ int   s_cnt[8][48];
    int tid = threadIdx.x;
    for (int i = tid; i < NT_ * 256; i += 256) s_hnt[i] = ((float*)g_hnt)[i];
    for (int i = tid; i < NT_*NT_*NR_*4; i += 256) s_tab[i] = g_tab0[i];
    if (tid < 64) s_b0[tid] = b0[tid];
    __syncthreads();

    int warp = tid >> 5, lane = tid & 31;
    int d = blockIdx.x * 8 + warp;
    if (d >= N_) return;

    if (lane < 24) { s_cnt[warp][lane] = 0; s_cnt[warp][lane + 24] = 0; }
    int nd = ntype[d];
    int start = g_row[d], deg = g_deg[d];
    __syncwarp();
    for (int k = lane; k < deg; k += 32) {
        int w = g_adj[start + k];
        int t = (w >> 16) & 7;
        int ns = (w >> 19) & 7;
        atomicAdd(&s_cnt[warp][ns * 6 + t], 1);
    }
    __syncwarp();

    int ns = lane >> 2, h = lane & 3;
    float A = 0.f;
#pragma unroll
    for (int t = 0; t < 6; t++)
        A += (float)s_cnt[warp][ns * 6 + t] * s_tab[((nd * 8 + ns) * 6 + t) * 4 + h];
    float den = A;
    den += __shfl_xor_sync(0xffffffffu, den, 4);
    den += __shfl_xor_sync(0xffffffffu, den, 8);
    den += __shfl_xor_sync(0xffffffffu, den, 16);
    float ainv = A / (den + 1e-16f);

    float v0 = 0.f, v1 = 0.f;
#pragma unroll
    for (int l2 = 0; l2 < 32; l2++) {
        float a = __shfl_sync(0xffffffffu, ainv, l2);
        int base = (l2 >> 2) * 256 + (l2 & 3) * 64;
        v0 += a * s_hnt[base + lane];
        v1 += a * s_hnt[base + lane + 32];
    }
    v0 = 0.25f * v0 + s_b0[lane];
    v1 = 0.25f * v1 + s_b0[lane + 32];
    g_x1f[d * 64 + lane]      = eluf(v0);
    g_x1f[d * 64 + lane + 32] = eluf(v1);
}

// ---------------- layer 1 GEMM + fused attn logits + bf16 pack ----------------
__global__ void __launch_bounds__(256) gemm_attn_kernel(const float* __restrict__ W1,
                                                        const float* __restrict__ att_src1,
                                                        const float* __restrict__ att_dst1) {
    extern __shared__ float smem[];
    float* sW    = smem;            // 16384
    float* sx    = smem + 16384;    // 4096
    float* s_as  = smem + 20480;    // 256
    float* s_ad  = smem + 20736;    // 256
    float* strns = smem + 20992;    // 8 warps * 256
    int tid = threadIdx.x;
    int n0 = blockIdx.x * 64;
    for (int i = tid; i < 16384; i += 256) sW[i] = W1[i];
    for (int i = tid; i < 4096; i += 256) {
        int m = i >> 6, k = i & 63;
        int n = n0 + m;
        sx[i] = (n < N_) ? g_x1f[n * 64 + k] : 0.f;
    }
    if (tid < 256) { s_as[tid] = att_src1[tid]; s_ad[tid] = att_dst1[tid]; }
    __syncthreads();
    int lane = tid & 31, ng = tid >> 5;
    float* sl = strns + ng * 256;
    float acc[8][8];
#pragma unroll
    for (int m = 0; m < 8; m++)
#pragma unroll
        for (int i = 0; i < 8; i++) acc[m][i] = 0.f;
    for (int k = 0; k < 64; k++) {
        float w[8];
#pragma unroll
        for (int i = 0; i < 8; i++) w[i] = sW[k * 256 + lane + 32 * i];
#pragma unroll
        for (int m = 0; m < 8; m++) {
            float xk = sx[(ng * 8 + m) * 64 + k];
#pragma unroll
            for (int i = 0; i < 8; i++) acc[m][i] += xk * w[i];
        }
    }
#pragma unroll
    for (int m = 0; m < 8; m++) {
        int n = n0 + ng * 8 + m;
        if (n >= N_) continue;
        // transpose via smem -> bf16 pack (lane owns cols lane*8..+7)
#pragma unroll
        for (int i = 0; i < 8; i++) sl[lane + 32 * i] = acc[m][i];
        __syncwarp();
        float4 u0 = *(float4*)&sl[lane * 8];
        float4 u1 = *(float4*)&sl[lane * 8 + 4];
        __syncwarp();
        uint4 pk;
        pk.x = bf2_to_u32(__float22bfloat162_rn(make_float2(u0.x, u0.y)));
        pk.y = bf2_to_u32(__float22bfloat162_rn(make_float2(u0.z, u0.w)));
        pk.z = bf2_to_u32(__float22bfloat162_rn(make_float2(u1.x, u1.y)));
        pk.w = bf2_to_u32(__float22bfloat162_rn(make_float2(u1.z, u1.w)));
        g_h1b[n * 32 + lane] = pk;
        // fused attn logits from fp32 accumulators
        float p[4] = {0.f,0.f,0.f,0.f}, q[4] = {0.f,0.f,0.f,0.f};
#pragma unroll
        for (int i = 0; i < 8; i++) {
            float v = acc[m][i];
            int hh = i >> 1;
            p[hh] += v * s_as[32 * i + lane];
            q[hh] += v * s_ad[32 * i + lane];
        }
#pragma unroll
        for (int off = 16; off >= 1; off >>= 1) {
#pragma unroll
            for (int hh = 0; hh < 4; hh++) {
                p[hh] += __shfl_xor_sync(0xffffffffu, p[hh], off);
                q[hh] += __shfl_xor_sync(0xffffffffu, q[hh], off);
            }
        }
        if (lane == 0) {
            g_as1[n] = make_float4(p[0], p[1], p[2], p[3]);
            g_ad1[n] = make_float4(q[0], q[1], q[2], q[3]);
        }
    }
}

// ---------------- layer 1 edge pass: warp/node, bf16 gather, ALU-only cvt ----------------
__global__ void __launch_bounds__(256) edge1_kernel(const int* __restrict__ batch,
                                                    const float* __restrict__ b1) {
    __shared__ float4 s_ae[NR_];
    __shared__ float  s_b1[64];
    __shared__ float4 s_w[8][32];
    __shared__ int    s_s[8][32];
    int tid = threadIdx.x;
    if (tid < NR_) s_ae[tid] = g_ae1[tid];
    if (tid < 64) s_b1[tid] = b1[tid];
    __syncthreads();

    int warp = tid >> 5, lane = tid & 31;
    int d = blockIdx.x * 8 + warp;
    if (d >= N_) return;

    float4 ad = g_ad1[d];
    int start = g_row[d], deg = g_deg[d];

    float f[8];
#pragma unroll
    for (int i = 0; i < 8; i++) f[i] = 0.f;
    float4 dacc = make_float4(0.f,0.f,0.f,0.f);

    for (int base = 0; base < deg; base += 32) {
        int k = base + lane;
        int s = 0;
        float4 e = make_float4(0.f,0.f,0.f,0.f);
        if (k < deg) {
            int w = g_adj[start + k];
            s = w & 0xffff;
            int t = (w >> 16) & 7;
            float4 as = __ldg(&g_as1[s]);
            float4 ae = s_ae[t];
            e.x = __expf(lrelu(as.x + ad.x + ae.x));
            e.y = __expf(lrelu(as.y + ad.y + ae.y));
            e.z = __expf(lrelu(as.z + ad.z + ae.z));
            e.w = __expf(lrelu(as.w + ad.w + ae.w));
            dacc.x += e.x; dacc.y += e.y; dacc.z += e.z; dacc.w += e.w;
        }
        s_s[warp][lane] = s;
        s_w[warp][lane] = e;
        __syncwarp();
        int cnt = min(32, deg - base);
#pragma unroll 8
        for (int j = 0; j < cnt; j++) {
            float4 e2 = s_w[warp][j];
            int s2 = s_s[warp][j];
            float wgt = (lane < 8) ? e2.x : (lane < 16) ? e2.y : (lane < 24) ? e2.z : e2.w;
            uint4 hv = g_h1b[s2 * 32 + lane];   // 8 bf16: cols lane*8..+7 (head lane>>3)
            f[0] += wgt * bf_lo(hv.x); f[1] += wgt * bf_hi(hv.x);
            f[2] += wgt * bf_lo(hv.y); f[3] += wgt * bf_hi(hv.y);
            f[4] += wgt * bf_lo(hv.z); f[5] += wgt * bf_hi(hv.z);
            f[6] += wgt * bf_lo(hv.w); f[7] += wgt * bf_hi(hv.w);
        }
        __syncwarp();
    }

#pragma unroll
    for (int off = 16; off >= 1; off >>= 1) {
        dacc.x += __shfl_xor_sync(0xffffffffu, dacc.x, off);
        dacc.y += __shfl_xor_sync(0xffffffffu, dacc.y, off);
        dacc.z += __shfl_xor_sync(0xffffffffu, dacc.z, off);
        dacc.w += __shfl_xor_sync(0xffffffffu, dacc.w, off);
    }
    float denh = (lane < 8) ? dacc.x : (lane < 16) ? dacc.y : (lane < 24) ? dacc.z : dacc.w;
    float inv = 1.f / (denh + 1e-16f);
#pragma unroll
    for (int i = 0; i < 8; i++) {
        f[i] *= inv;
        f[i] += __shfl_xor_sync(0xffffffffu, f[i], 8);
        f[i] += __shfl_xor_sync(0xffffffffu, f[i], 16);
    }
    if (lane < 8) {
        float4 o0, o1;
        o0.x = eluf(0.25f * f[0] + s_b1[lane * 8 + 0]);
        o0.y = eluf(0.25f * f[1] + s_b1[lane * 8 + 1]);
        o0.z = eluf(0.25f * f[2] + s_b1[lane * 8 + 2]);
        o0.w = eluf(0.25f * f[3] + s_b1[lane * 8 + 3]);
        o1.x = eluf(0.25f * f[4] + s_b1[lane * 8 + 4]);
        o1.y = eluf(0.25f * f[5] + s_b1[lane * 8 + 5]);
        o1.z = eluf(0.25f * f[6] + s_b1[lane * 8 + 6]);
        o1.w = eluf(0.25f * f[7] + s_b1[lane * 8 + 7]);
        int g = batch[d];
        red_add_f4(&g_pool[g * 16 + lane * 2], o0);
        red_add_f4(&g_pool[g * 16 + lane * 2 + 1], o1);
        if (lane == 0) atomicAdd(&g_cnt[g], 1.0f);
    }
}

// ---------------- classifier (1 block) ----------------
__global__ void cls_kernel(const float* __restrict__ cw1, const float* __restrict__ cb1,
                           const float* __restrict__ cw2, const float* __restrict__ cb2,
                           float* __restrict__ out) {
    __shared__ float sg[4096];
    __shared__ float st[4096];
    int tid = threadIdx.x;
    for (int i = tid; i < 4096; i += 256) {
        int g = i >> 6;
        float cnt = g_cnt[g];
        sg[i] = ((float*)g_pool)[i] / fmaxf(cnt, 1.f);
    }
    __syncthreads();
    for (int i = tid; i < 4096; i += 256) {
        int g = i >> 6, k = i & 63;
        float acc = cb1[k];
        for (int c = 0; c < 64; c++) acc += sg[g * 64 + c] * cw1[c * 64 + k];
        st[i] = fmaxf(acc, 0.f);
    }
    __syncthreads();
    if (tid < 128) {
        int g = tid >> 1, o = tid & 1;
        float acc = cb2[o];
        for (int k = 0; k < 64; k++) acc += st[g * 64 + k] * cw2[k * 2 + o];
        out[tid] = acc;
    }
}

// ---------------- launch ----------------
extern "C" void kernel_launch(void* const* d_in, const int* in_sizes, int n_in,
                              void* d_out, int out_size) {
    const int*   node_type = (const int*)d_in[0];
    const int*   edge_type = (const int*)d_in[1];
    const int*   ei        = (const int*)d_in[2];
    const int*   src = ei;
    const int*   dst = ei + E_;
    const int*   batch     = (const int*)d_in[3];
    const float* node_emb  = (const float*)d_in[4];
    const float* edge_emb  = (const float*)d_in[5];
    const float* W0   = (const float*)d_in[6];
    const float* We0  = (const float*)d_in[7];
    const float* as0  = (const float*)d_in[8];
    const float* ad0  = (const float*)d_in[9];
    const float* ae0  = (const float*)d_in[10];
    const float* b0   = (const float*)d_in[11];
    const float* W1   = (const float*)d_in[12];
    const float* We1  = (const float*)d_in[13];
    const float* as1  = (const float*)d_in[14];
    const float* ad1  = (const float*)d_in[15];
    const float* ae1  = (const float*)d_in[16];
    const float* b1   = (const float*)d_in[17];
    const float* cw1  = (const float*)d_in[18];
    const float* cb1  = (const float*)d_in[19];
    const float* cw2  = (const float*)d_in[20];
    const float* cb2  = (const float*)d_in[21];
    float* out = (float*)d_out;

    cudaFuncSetAttribute(gemm_attn_kernel, cudaFuncAttributeMaxDynamicSharedMemorySize, 94208);

    zero_small<<<NBLK, 256>>>();
    hist_kernel<<<(E_ + 255) / 256, 256>>>(dst);
    scanA_kernel<<<NBLK, 256>>>();
    scanB_kernel<<<1, 256>>>();
    scanC_kernel<<<NBLK, 256>>>();
    scatter_kernel<<<(E_ + 255) / 256, 256>>>(src, dst, edge_type, node_type);
    prep_kernel<<<NT_ + NR_, 256>>>(node_emb, edge_emb, W0, We0, as0, ad0, ae0, We1, ae1);
    prep2_kernel<<<6, 256>>>();
    layer0_kernel<<<(N_ + 7) / 8, 256>>>(node_type, b0);
    gemm_attn_kernel<<<(N_ + 63) / 64, 256, 94208>>>(W1, as1, ad1);
    edge1_kernel<<<(N_ + 7) / 8, 256>>>(batch, b1);
    cls_kernel<<<1, 256>>>(cw1, cb1, cw2, cb2, out);
}

// round 9
// speedup vs baseline: 1.3479x; 1.0578x over previous
#include <cuda_runtime.h>
#include <math.h>

#define N_    50000
#define E_    800000
#define G_    64
#define H_    4
#define C_    64
#define EDIM_ 16
#define NT_   8
#define NR_   6
#define NEG_  0.2f

#define NPAD  50176           // 196*256
#define NBLK  196

// ---------------- scratch (device globals) ----------------
__device__ float4 g_hnt[NT_ * 64];
__device__ float4 g_asnt[NT_];
__device__ float4 g_adnt[NT_];
__device__ float4 g_ae0[NR_];
__device__ float4 g_ae1[NR_];
__device__ float  g_tab0[NT_*NT_*NR_*4];
__device__ float  g_x1f[N_ * 64];
__device__ float4 g_h1[N_ * 64];          // fp32 h1: [n][256] = 64 float4/row
__device__ float4 g_as1[N_];
__device__ float4 g_ad1[N_];
__device__ float4 g_pool[1024];
__device__ float  g_cnt[64];
// CSR
__device__ int g_deg[NPAD];
__device__ int g_row[NPAD];
__device__ int g_cur[NPAD];
__device__ int g_bsum[256];
__device__ int g_boff[256];
__device__ int g_adj[E_];                 // (ns<<19)|(etype<<16)|src

__device__ __forceinline__ float lrelu(float v) { return v > 0.f ? v : NEG_ * v; }
__device__ __forceinline__ float eluf(float v)  { return v > 0.f ? v : expm1f(v); }

__device__ __forceinline__ void red_add_f4(float4* addr, float4 v) {
    asm volatile("red.global.add.v4.f32 [%0], {%1,%2,%3,%4};"
                 :: "l"(addr), "f"(v.x), "f"(v.y), "f"(v.z), "f"(v.w) : "memory");
}

// ---------------- zero small scratch ----------------
__global__ void zero_small() {
    int i = blockIdx.x * blockDim.x + threadIdx.x;
    if (i < NPAD) g_deg[i] = 0;
    if (i < 1024) g_pool[i] = make_float4(0.f, 0.f, 0.f, 0.f);
    if (i < 64)   g_cnt[i] = 0.f;
    if (i < 256)  { g_bsum[i] = 0; g_boff[i] = 0; }
}

// ---------------- CSR build (coalesced 3-phase scan) ----------------
__global__ void hist_kernel(const int* __restrict__ dst) {
    int e = blockIdx.x * blockDim.x + threadIdx.x;
    if (e < E_) atomicAdd(&g_deg[dst[e]], 1);
}

__global__ void scanA_kernel() {
    __shared__ int sh[256];
    int i = blockIdx.x * 256 + threadIdx.x;
    int v = g_deg[i];
    sh[threadIdx.x] = v;
    __syncthreads();
#pragma unroll
    for (int off = 1; off < 256; off <<= 1) {
        int t = (threadIdx.x >= off) ? sh[threadIdx.x - off] : 0;
        __syncthreads();
        sh[threadIdx.x] += t;
        __syncthreads();
    }
    g_row[i] = sh[threadIdx.x] - v;
    if (threadIdx.x == 255) g_bsum[blockIdx.x] = sh[255];
}

__global__ void scanB_kernel() {
    __shared__ int sh[256];
    int t = threadIdx.x;
    int v = g_bsum[t];
    sh[t] = v;
    __syncthreads();
#pragma unroll
    for (int off = 1; off < 256; off <<= 1) {
        int u = (t >= off) ? sh[t - off] : 0;
        __syncthreads();
        sh[t] += u;
        __syncthreads();
    }
    g_boff[t] = sh[t] - v;
}

__global__ void scanC_kernel() {
    int i = blockIdx.x * 256 + threadIdx.x;
    int r = g_row[i] + g_boff[blockIdx.x];
    g_row[i] = r;
    g_cur[i] = r;
}

__global__ void scatter_kernel(const int* __restrict__ src, const int* __restrict__ dst,
                               const int* __restrict__ et, const int* __restrict__ ntype) {
    int e = blockIdx.x * blockDim.x + threadIdx.x;
    if (e >= E_) return;
    int d = dst[e];
    int s = src[e];
    int ns = __ldg(&ntype[s]);
    int pos = atomicAdd(&g_cur[d], 1);
    g_adj[pos] = (ns << 19) | (et[e] << 16) | s;
}

// ---------------- precompute type tables (14 blocks) ----------------
__global__ void prep_kernel(const float* __restrict__ node_emb,
                            const float* __restrict__ edge_emb,
                            const float* __restrict__ W0,
                            const float* __restrict__ We0,
                            const float* __restrict__ as0,
                            const float* __restrict__ ad0,
                            const float* __restrict__ ae0,
                            const float* __restrict__ We1,
                            const float* __restrict__ ae1) {
    int j = threadIdx.x;
    __shared__ float red_s[8];
    if (j < 8) red_s[j] = 0.f;
    __syncthreads();

    if (blockIdx.x < NT_) {
        int nt = blockIdx.x;
        float acc = 0.f;
        for (int k = 0; k < 64; k++) acc += node_emb[nt * 64 + k] * W0[k * 256 + j];
        ((float*)g_hnt)[nt * 256 + j] = acc;
        atomicAdd(&red_s[j >> 6],       acc * as0[j]);
        atomicAdd(&red_s[4 + (j >> 6)], acc * ad0[j]);
        __syncthreads();
        if (j < 4)      ((float*)g_asnt)[nt * 4 + j]       = red_s[j];
        else if (j < 8) ((float*)g_adnt)[nt * 4 + (j - 4)] = red_s[j];
    } else {
        int t = blockIdx.x - NT_;
        float h0 = 0.f, h1 = 0.f;
        for (int k = 0; k < EDIM_; k++) {
            float ev = edge_emb[t * EDIM_ + k];
            h0 += ev * We0[k * 256 + j];
            h1 += ev * We1[k * 256 + j];
        }
        atomicAdd(&red_s[j >> 6],       h0 * ae0[j]);
        atomicAdd(&red_s[4 + (j >> 6)], h1 * ae1[j]);
        __syncthreads();
        if (j < 4)      ((float*)g_ae0)[t * 4 + j]       = red_s[j];
        else if (j < 8) ((float*)g_ae1)[t * 4 + (j - 4)] = red_s[j];
    }
}

__global__ void prep2_kernel() {
    int idx = blockIdx.x * 256 + threadIdx.x;
    if (idx >= NT_*NT_*NR_*4) return;
    int h  = idx & 3;
    int r  = idx >> 2;
    int t  = r % 6;
    int r2 = r / 6;
    int ns = r2 & 7;
    int nd = r2 >> 3;
    float v = ((float*)g_asnt)[ns*4+h] + ((float*)g_adnt)[nd*4+h] + ((float*)g_ae0)[t*4+h];
    g_tab0[idx] = __expf(lrelu(v));
}

// ---------------- layer 0: warp per dst node (8 nodes/block) ----------------
__global__ void __launch_bounds__(256) layer0_kernel(const int* __restrict__ ntype,
                                                     const float* __restrict__ b0) {
    __shared__ float s_hnt[NT_ * 256];
    __shared__ float s_tab[NT_*NT_*NR_*4];
    __shared__ float s_b0[64];
    __shared__ int   s_cnt[8][48];
    int tid = threadIdx.x;
    for (int i = tid; i < NT_ * 256; i += 256) s_hnt[i] = ((float*)g_hnt)[i];
    for (int i = tid; i < NT_*NT_*NR_*4; i += 256) s_tab[i] = g_tab0[i];
    if (tid < 64) s_b0[tid] = b0[tid];
    __syncthreads();

    int warp = tid >> 5, lane = tid & 31;
    int d = blockIdx.x * 8 + warp;
    if (d >= N_) return;

    if (lane < 24) { s_cnt[warp][lane] = 0; s_cnt[warp][lane + 24] = 0; }
    int nd = ntype[d];
    int start = g_row[d], deg = g_deg[d];
    __syncwarp();
    for (int k = lane; k < deg; k += 32) {
        int w = g_adj[start + k];
        int t = (w >> 16) & 7;
        int ns = (w >> 19) & 7;
        atomicAdd(&s_cnt[warp][ns * 6 + t], 1);
    }
    __syncwarp();

    int ns = lane >> 2, h = lane & 3;
    float A = 0.f;
#pragma unroll
    for (int t = 0; t < 6; t++)
        A += (float)s_cnt[warp][ns * 6 + t] * s_tab[((nd * 8 + ns) * 6 + t) * 4 + h];
    float den = A;
    den += __shfl_xor_sync(0xffffffffu, den, 4);
    den += __shfl_xor_sync(0xffffffffu, den, 8);
    den += __shfl_xor_sync(0xffffffffu, den, 16);
    float ainv = A / (den + 1e-16f);

    float v0 = 0.f, v1 = 0.f;
#pragma unroll
    for (int l2 = 0; l2 < 32; l2++) {
        float a = __shfl_sync(0xffffffffu, ainv, l2);
        int base = (l2 >> 2) * 256 + (l2 & 3) * 64;
        v0 += a * s_hnt[base + lane];
        v1 += a * s_hnt[base + lane + 32];
    }
    v0 = 0.25f * v0 + s_b0[lane];
    v1 = 0.25f * v1 + s_b0[lane + 32];
    g_x1f[d * 64 + lane]      = eluf(v0);
    g_x1f[d * 64 + lane + 32] = eluf(v1);
}

// ---------------- layer 1 GEMM + fused attn logits (fp32 h1 store) ----------------
__global__ void __launch_bounds__(256) gemm_attn_kernel(const float* __restrict__ W1,
                                                        const float* __restrict__ att_src1,
                                                        const float* __restrict__ att_dst1) {
    extern __shared__ float smem[];
    float* sW    = smem;            // 16384
    float* sx    = smem + 16384;    // 4096
    float* s_as  = smem + 20480;    // 256
    float* s_ad  = smem + 20736;    // 256
    int tid = threadIdx.x;
    int n0 = blockIdx.x * 64;
    for (int i = tid; i < 16384; i += 256) sW[i] = W1[i];
    for (int i = tid; i < 4096; i += 256) {
        int m = i >> 6, k = i & 63;
        int n = n0 + m;
        sx[i] = (n < N_) ? g_x1f[n * 64 + k] : 0.f;
    }
    if (tid < 256) { s_as[tid] = att_src1[tid]; s_ad[tid] = att_dst1[tid]; }
    __syncthreads();
    int lane = tid & 31, ng = tid >> 5;
    float acc[8][8];
#pragma unroll
    for (int m = 0; m < 8; m++)
#pragma unroll
        for (int i = 0; i < 8; i++) acc[m][i] = 0.f;
    for (int k = 0; k < 64; k++) {
        float w[8];
#pragma unroll
        for (int i = 0; i < 8; i++) w[i] = sW[k * 256 + lane + 32 * i];
#pragma unroll
        for (int m = 0; m < 8; m++) {
            float xk = sx[(ng * 8 + m) * 64 + k];
#pragma unroll
            for (int i = 0; i < 8; i++) acc[m][i] += xk * w[i];
        }
    }
    float* h1f = (float*)g_h1;
#pragma unroll
    for (int m = 0; m < 8; m++) {
        int n = n0 + ng * 8 + m;
        if (n >= N_) continue;
#pragma unroll
        for (int i = 0; i < 8; i++)
            h1f[n * 256 + lane + 32 * i] = acc[m][i];
        // fused attn logits from fp32 accumulators
        float p[4] = {0.f,0.f,0.f,0.f}, q[4] = {0.f,0.f,0.f,0.f};
#pragma unroll
        for (int i = 0; i < 8; i++) {
            float v = acc[m][i];
            int hh = i >> 1;
            p[hh] += v * s_as[32 * i + lane];
            q[hh] += v * s_ad[32 * i + lane];
        }
#pragma unroll
        for (int off = 16; off >= 1; off >>= 1) {
#pragma unroll
            for (int hh = 0; hh < 4; hh++) {
                p[hh] += __shfl_xor_sync(0xffffffffu, p[hh], off);
                q[hh] += __shfl_xor_sync(0xffffffffu, q[hh], off);
            }
        }
        if (lane == 0) {
            g_as1[n] = make_float4(p[0], p[1], p[2], p[3]);
            g_ad1[n] = make_float4(q[0], q[1], q[2], q[3]);
        }
    }
}

// ---------------- layer 1 edge pass: warp/node, fp32 gather (R3-proven loop) ----------------
__global__ void __launch_bounds__(256) edge1_kernel(const int* __restrict__ batch,
                                                    const float* __restrict__ b1) {
    __shared__ float4 s_ae[NR_];
    __shared__ float  s_b1[64];
    __shared__ float4 s_w[8][32];
    __shared__ int    s_s[8][32];
    int tid = threadIdx.x;
    if (tid < NR_) s_ae[tid] = g_ae1[tid];
    if (tid < 64) s_b1[tid] = b1[tid];
    __syncthreads();

    int warp = tid >> 5, lane = tid & 31;
    int d = blockIdx.x * 8 + warp;
    if (d >= N_) return;

    float4 ad = g_ad1[d];
    int start = g_row[d], deg = g_deg[d];
    int hsel = lane >> 4;   // 0 or 1

    float4 f0 = make_float4(0.f,0.f,0.f,0.f);
    float4 f1 = make_float4(0.f,0.f,0.f,0.f);
    float4 dacc = make_float4(0.f,0.f,0.f,0.f);

    for (int base = 0; base < deg; base += 32) {
        int k = base + lane;
        int s = 0;
        float4 e = make_float4(0.f,0.f,0.f,0.f);
        if (k < deg) {
            int w = g_adj[start + k];
            s = w & 0xffff;
            int t = (w >> 16) & 7;
            float4 as = __ldg(&g_as1[s]);
            float4 ae = s_ae[t];
            e.x = __expf(lrelu(as.x + ad.x + ae.x));
            e.y = __expf(lrelu(as.y + ad.y + ae.y));
            e.z = __expf(lrelu(as.z + ad.z + ae.z));
            e.w = __expf(lrelu(as.w + ad.w + ae.w));
            dacc.x += e.x; dacc.y += e.y; dacc.z += e.z; dacc.w += e.w;
        }
        s_s[warp][lane] = s;
        s_w[warp][lane] = e;
        __syncwarp();
        int cnt = min(32, deg - base);
#pragma unroll 4
        for (int j = 0; j < cnt; j++) {
            float4 e2 = s_w[warp][j];
            int s2 = s_s[warp][j];
            float wlo = hsel ? e2.y : e2.x;
            float whi = hsel ? e2.w : e2.z;
            float4 h0 = g_h1[s2 * 64 + lane];
            float4 hv = g_h1[s2 * 64 + 32 + lane];
            f0.x += wlo * h0.x; f0.y += wlo * h0.y; f0.z += wlo * h0.z; f0.w += wlo * h0.w;
            f1.x += whi * hv.x; f1.y += whi * hv.y; f1.z += whi * hv.z; f1.w += whi * hv.w;
        }
        __syncwarp();
    }

#pragma unroll
    for (int off = 16; off >= 1; off >>= 1) {
        dacc.x += __shfl_xor_sync(0xffffffffu, dacc.x, off);
        dacc.y += __shfl_xor_sync(0xffffffffu, dacc.y, off);
        dacc.z += __shfl_xor_sync(0xffffffffu, dacc.z, off);
        dacc.w += __shfl_xor_sync(0xffffffffu, dacc.w, off);
    }
    float invlo = 1.f / ((hsel ? dacc.y : dacc.x) + 1e-16f);
    float invhi = 1.f / ((hsel ? dacc.w : dacc.z) + 1e-16f);
    float4 p;
    p.x = f0.x * invlo + f1.x * invhi;
    p.y = f0.y * invlo + f1.y * invhi;
    p.z = f0.z * invlo + f1.z * invhi;
    p.w = f0.w * invlo + f1.w * invhi;
    p.x += __shfl_xor_sync(0xffffffffu, p.x, 16);
    p.y += __shfl_xor_sync(0xffffffffu, p.y, 16);
    p.z += __shfl_xor_sync(0xffffffffu, p.z, 16);
    p.w += __shfl_xor_sync(0xffffffffu, p.w, 16);

    if (lane < 16) {
        int c0 = lane * 4;
        float4 o;
        o.x = eluf(0.25f * p.x + s_b1[c0]);
        o.y = eluf(0.25f * p.y + s_b1[c0 + 1]);
        o.z = eluf(0.25f * p.z + s_b1[c0 + 2]);
        o.w = eluf(0.25f * p.w + s_b1[c0 + 3]);
        int g = batch[d];
        red_add_f4(&g_pool[g * 16 + lane], o);
        if (lane == 0) atomicAdd(&g_cnt[g], 1.0f);
    }
}

// ---------------- classifier (1 block) ----------------
__global__ void cls_kernel(const float* __restrict__ cw1, const float* __restrict__ cb1,
                           const float* __restrict__ cw2, const float* __restrict__ cb2,
                           float* __restrict__ out) {
    __shared__ float sg[4096];
    __shared__ float st[4096];
    int tid = threadIdx.x;
    for (int i = tid; i < 4096; i += 256) {
        int g = i >> 6;
        float cnt = g_cnt[g];
        sg[i] = ((float*)g_pool)[i] / fmaxf(cnt, 1.f);
    }
    __syncthreads();
    for (int i = tid; i < 4096; i += 256) {
        int g = i >> 6, k = i & 63;
        float acc = cb1[k];
        for (int c = 0; c < 64; c++) acc += sg[g * 64 + c] * cw1[c * 64 + k];
        st[i] = fmaxf(acc, 0.f);
    }
    __syncthreads();
    if (tid < 128) {
        int g = tid >> 1, o = tid & 1;
        float acc = cb2[o];
        for (int k = 0; k < 64; k++) acc += st[g * 64 + k] * cw2[k * 2 + o];
        out[tid] = acc;
    }
}

// ---------------- launch ----------------
extern "C" void kernel_launch(void* const* d_in, const int* in_sizes, int n_in,
                              void* d_out, int out_size) {
    const int*   node_type = (const int*)d_in[0];
    const int*   edge_type = (const int*)d_in[1];
    const int*   ei        = (const int*)d_in[2];
    const int*   src = ei;
    const int*   dst = ei + E_;
    const int*   batch     = (const int*)d_in[3];
    const float* node_emb  = (const float*)d_in[4];
    const float* edge_emb  = (const float*)d_in[5];
    const float* W0   = (const float*)d_in[6];
    const float* We0  = (const float*)d_in[7];
    const float* as0  = (const float*)d_in[8];
    const float* ad0  = (const float*)d_in[9];
    const float* ae0  = (const float*)d_in[10];
    const float* b0   = (const float*)d_in[11];
    const float* W1   = (const float*)d_in[12];
    const float* We1  = (const float*)d_in[13];
    const float* as1  = (const float*)d_in[14];
    const float* ad1  = (const float*)d_in[15];
    const float* ae1  = (const float*)d_in[16];
    const float* b1   = (const float*)d_in[17];
    const float* cw1  = (const float*)d_in[18];
    const float* cb1  = (const float*)d_in[19];
    const float* cw2  = (const float*)d_in[20];
    const float* cb2  = (const float*)d_in[21];
    float* out = (float*)d_out;

    cudaFuncSetAttribute(gemm_attn_kernel, cudaFuncAttributeMaxDynamicSharedMemorySize, 86016);

    zero_small<<<NBLK, 256>>>();
    hist_kernel<<<(E_ + 255) / 256, 256>>>(dst);
    scanA_kernel<<<NBLK, 256>>>();
    scanB_kernel<<<1, 256>>>();
    scanC_kernel<<<NBLK, 256>>>();
    scatter_kernel<<<(E_ + 255) / 256, 256>>>(src, dst, edge_type, node_type);
    prep_kernel<<<NT_ + NR_, 256>>>(node_emb, edge_emb, W0, We0, as0, ad0, ae0, We1, ae1);
    prep2_kernel<<<6, 256>>>();
    layer0_kernel<<<(N_ + 7) / 8, 256>>>(node_type, b0);
    gemm_attn_kernel<<<(N_ + 63) / 64, 256, 86016>>>(W1, as1, ad1);
    edge1_kernel<<<(N_ + 7) / 8, 256>>>(batch, b1);
    cls_kernel<<<1, 256>>>(cw1, cb1, cw2, cb2, out);
}